// round 2
// baseline (speedup 1.0000x reference)
#include <cuda_runtime.h>
#include <cuda_bf16.h>
#include <math.h>

// ---------------- problem constants ----------------
#define BB   4
#define SS   2048
#define DD   1024
#define HH   16
#define DHH  64
#define FFD  4096
#define WINW 16
#define GMD  64
#define RR   512
#define NWIN (SS / WINW)          // 128
#define TT   (BB * SS)            // 8192 tokens
#define PP   (SS / 2)             // 1024 pairs per batch
#define KEEPN (SS - RR)           // 1536 kept per batch

// output offsets (float32 concatenation of the 4 outputs)
#define X_OUT_OFF   ((size_t)0)
#define SRC_OUT_OFF ((size_t)BB * KEEPN * DD)                       // 6291456
#define POS_OUT_OFF (SRC_OUT_OFF + (size_t)BB * KEEPN * SS)         // 18874368
#define SP_OUT_OFF  (POS_OUT_OFF + (size_t)BB * KEEPN)              // 18880512

// ---------------- scratch (static device buffers; no allocation) ----------------
__device__ float g_x1[(size_t)TT * DD];      // x + span-embed; later x2, then x3
__device__ float g_h [(size_t)TT * DD];      // h (rms1), later h2 (rms2)
__device__ float g_q [(size_t)TT * DD];      // q; attention output o written in-place
__device__ float g_k [(size_t)TT * DD];
__device__ float g_v [(size_t)TT * DD];
__device__ float g_f1[(size_t)TT * FFD];     // h2@w1 -> silu(f1)*f2
__device__ float g_f2[(size_t)TT * FFD];     // h2@w3
__device__ float g_metric[(size_t)TT * GMD];
__device__ float g_sim [BB * PP];
__device__ int   g_flag[BB * PP];
__device__ int   g_pf  [BB * PP];
__device__ int   g_real[BB * SS];

// ---------------- elementwise / norm kernels ----------------

__global__ void span_add_kernel(const float* __restrict__ x, const int* __restrict__ span,
                                const float* __restrict__ w_span) {
    int row = blockIdx.x;                  // token index
    float se = log1pf((float)span[row]);
    const float4* xr = (const float4*)(x + (size_t)row * DD);
    const float4* wr = (const float4*)w_span;
    float4* o = (float4*)(g_x1 + (size_t)row * DD);
    int t = threadIdx.x;                   // 256 threads, 1 float4 each
    float4 a = xr[t], w = wr[t];
    o[t] = make_float4(a.x + se * w.x, a.y + se * w.y, a.z + se * w.z, a.w + se * w.w);
}

__global__ void rms_kernel(const float* __restrict__ x, const float* __restrict__ w,
                           float* __restrict__ out) {
    int row = blockIdx.x;
    const float4* xr = (const float4*)(x + (size_t)row * DD);
    int t = threadIdx.x;                   // 256 threads, 1 float4 each
    float4 a = xr[t];
    float ss = a.x * a.x + a.y * a.y + a.z * a.z + a.w * a.w;
    for (int off = 16; off > 0; off >>= 1) ss += __shfl_xor_sync(0xffffffffu, ss, off);
    __shared__ float red[8];
    if ((t & 31) == 0) red[t >> 5] = ss;
    __syncthreads();
    if (t < 8) {
        float v = red[t];
        for (int off = 4; off > 0; off >>= 1) v += __shfl_xor_sync(0xffu, v, off);
        if (t == 0) red[0] = v;
    }
    __syncthreads();
    float scale = rsqrtf(red[0] / (float)DD + 1e-6f);
    const float4* wr = (const float4*)w;
    float4 wv = wr[t];
    float4* o = (float4*)(out + (size_t)row * DD);
    o[t] = make_float4(a.x * scale * wv.x, a.y * scale * wv.y,
                       a.z * scale * wv.z, a.w * scale * wv.w);
}

// ---------------- SGEMM 128x128x16: C[M,N] = A[M,K] * W[K,N] (+residual) ------
// 256 threads (16x16), each computes an 8x8 micro-tile (split 4+4 in each dim).
template <int ADD>
__global__ void __launch_bounds__(256, 1)
sgemm128_kernel(const float* __restrict__ A, const float* __restrict__ W,
                const float* __restrict__ Rsrc, float* __restrict__ C,
                int M, int N, int K) {
    __shared__ float As[16][128];   // transposed A tile: As[k][m]
    __shared__ float Ws[16][128];   // W tile: Ws[k][n]
    int tx = threadIdx.x & 15, ty = threadIdx.x >> 4;
    int tid = threadIdx.x;
    int bm = blockIdx.y * 128, bn = blockIdx.x * 128;
    float acc[8][8] = {};

    for (int k0 = 0; k0 < K; k0 += 16) {
        // A tile: 128 rows x 16 cols -> 512 float4 loads / 256 threads = 2 each
#pragma unroll
        for (int i = 0; i < 2; i++) {
            int idx = tid + i * 256;
            int r = idx >> 2, c4 = (idx & 3) << 2;
            float4 a = *(const float4*)(A + (size_t)(bm + r) * K + k0 + c4);
            As[c4 + 0][r] = a.x; As[c4 + 1][r] = a.y;
            As[c4 + 2][r] = a.z; As[c4 + 3][r] = a.w;
        }
        // W tile: 16 rows x 128 cols -> 512 float4 loads / 256 threads = 2 each
#pragma unroll
        for (int i = 0; i < 2; i++) {
            int idx = tid + i * 256;
            int r = idx >> 5, c4 = (idx & 31) << 2;
            *(float4*)(&Ws[r][c4]) = *(const float4*)(W + (size_t)(k0 + r) * N + bn + c4);
        }
        __syncthreads();
#pragma unroll
        for (int kk = 0; kk < 16; kk++) {
            float4 a0 = *(const float4*)(&As[kk][ty * 4]);
            float4 a1 = *(const float4*)(&As[kk][64 + ty * 4]);
            float4 b0 = *(const float4*)(&Ws[kk][tx * 4]);
            float4 b1 = *(const float4*)(&Ws[kk][64 + tx * 4]);
            float av[8] = {a0.x, a0.y, a0.z, a0.w, a1.x, a1.y, a1.z, a1.w};
            float bw[8] = {b0.x, b0.y, b0.z, b0.w, b1.x, b1.y, b1.z, b1.w};
#pragma unroll
            for (int i = 0; i < 8; i++)
#pragma unroll
                for (int j = 0; j < 8; j++) acc[i][j] += av[i] * bw[j];
        }
        __syncthreads();
    }
    // epilogue: rows {bm+ty*4+i, bm+64+ty*4+i}, cols {bn+tx*4+j, bn+64+tx*4+j}
#pragma unroll
    for (int i = 0; i < 8; i++) {
        int m = bm + (i < 4 ? ty * 4 + i : 64 + ty * 4 + (i - 4));
#pragma unroll
        for (int jh = 0; jh < 2; jh++) {
            int n = bn + jh * 64 + tx * 4;
            float4 v = make_float4(acc[i][jh * 4 + 0], acc[i][jh * 4 + 1],
                                   acc[i][jh * 4 + 2], acc[i][jh * 4 + 3]);
            if (ADD) {
                float4 rr = *(const float4*)(Rsrc + (size_t)m * N + n);
                v.x += rr.x; v.y += rr.y; v.z += rr.z; v.w += rr.w;
            }
            *(float4*)(C + (size_t)m * N + n) = v;
        }
    }
}

// ---------------- SGEMM 64x64 (for N=64 metric GEMM) ----------------
__global__ void sgemm64_kernel(const float* __restrict__ A, const float* __restrict__ W,
                               float* __restrict__ C, int M, int N, int K) {
    __shared__ float As[16][68];
    __shared__ float Ws[16][68];
    int tx = threadIdx.x, ty = threadIdx.y;
    int tid = ty * 16 + tx;
    int bm = blockIdx.y * 64, bn = blockIdx.x * 64;
    float acc[4][4] = {};
    for (int k0 = 0; k0 < K; k0 += 16) {
        {
            int r = tid >> 2, c = (tid & 3) * 4;
            float4 a = *(const float4*)(A + (size_t)(bm + r) * K + k0 + c);
            As[c + 0][r] = a.x; As[c + 1][r] = a.y; As[c + 2][r] = a.z; As[c + 3][r] = a.w;
        }
        {
            int r = tid >> 4, c = (tid & 15) * 4;
            *(float4*)(&Ws[r][c]) = *(const float4*)(W + (size_t)(k0 + r) * N + bn + c);
        }
        __syncthreads();
#pragma unroll
        for (int kk = 0; kk < 16; kk++) {
            float4 a = *(const float4*)(&As[kk][ty * 4]);
            float4 b = *(const float4*)(&Ws[kk][tx * 4]);
            float av[4] = {a.x, a.y, a.z, a.w};
            float bw[4] = {b.x, b.y, b.z, b.w};
#pragma unroll
            for (int i = 0; i < 4; i++)
#pragma unroll
                for (int j = 0; j < 4; j++) acc[i][j] += av[i] * bw[j];
        }
        __syncthreads();
    }
#pragma unroll
    for (int i = 0; i < 4; i++) {
        int m = bm + ty * 4 + i;
#pragma unroll
        for (int j = 0; j < 4; j++) {
            int n = bn + tx * 4 + j;
            C[(size_t)m * N + n] = acc[i][j];
        }
    }
}

// ---------------- RoPE (in place on q and k) ----------------
__global__ void rope_kernel(float* __restrict__ q, float* __restrict__ k,
                            const int* __restrict__ pos, const float* __restrict__ freqs) {
    int row = blockIdx.x;                 // token
    int t = threadIdx.x;                  // 512 = H(16) * 32 pairs
    int h = t >> 5, dp = t & 31;
    float ang = (float)pos[row] * freqs[dp];
    float c = cosf(ang), s = sinf(ang);
    size_t base = (size_t)row * DD + h * DHH + dp;
    float a = q[base], b = q[base + 32];
    q[base] = a * c - b * s; q[base + 32] = a * s + b * c;
    a = k[base]; b = k[base + 32];
    k[base] = a * c - b * s; k[base + 32] = a * s + b * c;
}

// ---------------- windowed attention; writes o in-place into q ----------------
__global__ void attn_kernel(float* __restrict__ q, const float* __restrict__ k,
                            const float* __restrict__ v) {
    int blk = blockIdx.x;
    int head = blk % HH;
    int win = (blk / HH) % NWIN;
    int b = blk / (HH * NWIN);
    int s0 = b * SS + win * WINW;

    __shared__ float sq[16][68], sk[16][68], sv[16][68], sp[16][17];
    int tid = threadIdx.x;                // 256
    {
        int r = tid >> 4, c = (tid & 15) * 4;
        size_t g = (size_t)(s0 + r) * DD + head * DHH + c;
        *(float4*)(&sq[r][c]) = *(const float4*)(q + g);
        *(float4*)(&sk[r][c]) = *(const float4*)(k + g);
        *(float4*)(&sv[r][c]) = *(const float4*)(v + g);
    }
    __syncthreads();

    int qi = tid >> 4, ki = tid & 15;
    float sc = 0.f;
#pragma unroll
    for (int d = 0; d < DHH; d++) sc += sq[qi][d] * sk[ki][d];
    sc *= 0.125f;
    float m = sc;
#pragma unroll
    for (int off = 8; off > 0; off >>= 1) m = fmaxf(m, __shfl_xor_sync(0xffffffffu, m, off, 16));
    float e = expf(sc - m);
    float su = e;
#pragma unroll
    for (int off = 8; off > 0; off >>= 1) su += __shfl_xor_sync(0xffffffffu, su, off, 16);
    sp[qi][ki] = e / su;
    __syncthreads();

    int dg = tid & 15;
    float4 acc = make_float4(0.f, 0.f, 0.f, 0.f);
#pragma unroll
    for (int kk = 0; kk < 16; kk++) {
        float p = sp[qi][kk];
        acc.x += p * sv[kk][dg * 4 + 0];
        acc.y += p * sv[kk][dg * 4 + 1];
        acc.z += p * sv[kk][dg * 4 + 2];
        acc.w += p * sv[kk][dg * 4 + 3];
    }
    size_t go = (size_t)(s0 + qi) * DD + head * DHH + dg * 4;
    *(float4*)(q + go) = acc;
}

// ---------------- silu(f1)*f2 -> f1 ----------------
__global__ void silu_mul_kernel() {
    size_t i = ((size_t)blockIdx.x * blockDim.x + threadIdx.x);
    float4 a = ((const float4*)g_f1)[i];
    float4 b = ((const float4*)g_f2)[i];
    a.x = a.x / (1.f + expf(-a.x)) * b.x;
    a.y = a.y / (1.f + expf(-a.y)) * b.y;
    a.z = a.z / (1.f + expf(-a.z)) * b.z;
    a.w = a.w / (1.f + expf(-a.w)) * b.w;
    ((float4*)g_f1)[i] = a;
}

// ---------------- metric normalization ----------------
__global__ void norm_metric_kernel() {
    int row = blockIdx.x;
    int t = threadIdx.x;                  // 32
    float* mr = g_metric + (size_t)row * GMD;
    float a = mr[t], b = mr[t + 32];
    float ss = a * a + b * b;
#pragma unroll
    for (int off = 16; off > 0; off >>= 1) ss += __shfl_xor_sync(0xffffffffu, ss, off);
    float inv = 1.f / (sqrtf(ss) + 1e-6f);
    mr[t] = a * inv; mr[t + 32] = b * inv;
}

// ---------------- real[b,s] = sum_j source[b,s,j]*pad[b,j] > 0 ----------------
__global__ void real_kernel(const float* __restrict__ source, const float* __restrict__ pad) {
    int row = blockIdx.x;
    int b = row / SS;
    const float* sr = source + (size_t)row * SS;
    const float* pr = pad + (size_t)b * SS;
    float su = 0.f;
    for (int j = threadIdx.x; j < SS; j += 256) su += sr[j] * pr[j];
    for (int off = 16; off > 0; off >>= 1) su += __shfl_xor_sync(0xffffffffu, su, off);
    __shared__ float red[8];
    if ((threadIdx.x & 31) == 0) red[threadIdx.x >> 5] = su;
    __syncthreads();
    if (threadIdx.x == 0) {
        float tot = 0.f;
        for (int i = 0; i < 8; i++) tot += red[i];
        g_real[row] = (tot > 0.f) ? 1 : 0;
    }
}

// ---------------- sim[b,p] ----------------
__global__ void sim_kernel() {
    int bp = blockIdx.x;
    int b = bp / PP, p = bp % PP;
    int t = threadIdx.x;                  // 32
    const float* me = g_metric + ((size_t)b * SS + 2 * p) * GMD;
    const float* mo = me + GMD;
    float d = me[t] * mo[t] + me[t + 32] * mo[t + 32];
#pragma unroll
    for (int off = 16; off > 0; off >>= 1) d += __shfl_xor_sync(0xffffffffu, d, off);
    if (t == 0) {
        int ok = g_real[b * SS + 2 * p] & g_real[b * SS + 2 * p + 1];
        g_sim[bp] = ok ? d : -10000.0f;
    }
}

// ---------------- per-batch top-k(512): bitonic sort + flags + prefix scan ----
__global__ void topk_kernel() {
    int b = blockIdx.x;
    int tid = threadIdx.x;                // 1024
    __shared__ float val[1024];
    __shared__ int idx[1024];
    __shared__ int sf[1024];
    __shared__ int sc[1024];
    val[tid] = g_sim[b * PP + tid];
    idx[tid] = tid;
    __syncthreads();
    for (int k = 2; k <= 1024; k <<= 1) {
        for (int j = k >> 1; j > 0; j >>= 1) {
            int ixj = tid ^ j;
            if (ixj > tid) {
                bool dirDesc = ((tid & k) == 0);
                float v1 = val[tid], v2 = val[ixj];
                int i1 = idx[tid], i2 = idx[ixj];
                bool firstHigher = (v1 > v2) || (v1 == v2 && i1 < i2);
                if (dirDesc ? !firstHigher : firstHigher) {
                    val[tid] = v2; val[ixj] = v1;
                    idx[tid] = i2; idx[ixj] = i1;
                }
            }
            __syncthreads();
        }
    }
    sf[tid] = 0;
    __syncthreads();
    if (tid < RR) sf[idx[tid]] = 1;
    __syncthreads();
    int f = sf[tid];
    g_flag[b * PP + tid] = f;
    sc[tid] = f;
    __syncthreads();
    for (int off = 1; off < 1024; off <<= 1) {
        int t = (tid >= off) ? sc[tid - off] : 0;
        __syncthreads();
        sc[tid] += t;
        __syncthreads();
    }
    g_pf[b * PP + tid] = sc[tid] - f;
}

// ---------------- merge + compact + gather all 4 outputs ----------------
__global__ void gather_kernel(const float* __restrict__ source, const int* __restrict__ pos,
                              const int* __restrict__ span, float* __restrict__ out) {
    int b = blockIdx.y, s = blockIdx.x;
    int p = s >> 1;
    int f = g_flag[b * PP + p];
    bool odd = s & 1;
    if (odd && f) return;
    int j = s - g_pf[b * PP + p];
    int tid = threadIdx.x;                // 256

    const float* xr = g_x1 + ((size_t)b * SS + s) * DD;
    float* xo = out + X_OUT_OFF + ((size_t)b * KEEPN + j) * DD;
    if (!odd && f) {
        float sze = (float)span[b * SS + s];
        float szo = (float)span[b * SS + s + 1];
        float inv = 1.f / (sze + szo);
        const float* xr2 = xr + DD;
        for (int d = tid; d < DD; d += 256) xo[d] = (sze * xr[d] + szo * xr2[d]) * inv;
    } else {
        for (int d = tid; d < DD; d += 256) xo[d] = xr[d];
    }
    const float* sr = source + ((size_t)b * SS + s) * SS;
    float* so = out + SRC_OUT_OFF + ((size_t)b * KEEPN + j) * SS;
    if (!odd && f) {
        const float* sr2 = sr + SS;
        for (int t = tid; t < SS; t += 256) so[t] = sr[t] + sr2[t];
    } else {
        for (int t = tid; t < SS; t += 256) so[t] = sr[t];
    }
    if (tid == 0) {
        out[POS_OUT_OFF + (size_t)b * KEEPN + j] = (float)pos[b * SS + s];
        int sp = span[b * SS + s];
        if (!odd && f) sp += span[b * SS + s + 1];
        out[SP_OUT_OFF + (size_t)b * KEEPN + j] = (float)sp;
    }
}

// ---------------- launch ----------------
extern "C" void kernel_launch(void* const* d_in, const int* in_sizes, int n_in,
                              void* d_out, int out_size) {
    int p = 0;
    const float* x        = (const float*)d_in[p++];
    const float* source   = (const float*)d_in[p++];
    const int*   pos      = (const int*)  d_in[p++];
    const int*   span     = (const int*)  d_in[p++];
    if (p < n_in && in_sizes[p] == 1) p++;            // scalar r, if passed
    const float* freqs    = (const float*)d_in[p++];
    const float* pad_mask = (const float*)d_in[p++];
    p++;                                               // seq_pad_mask (all true; unused)
    const float* w_span   = (const float*)d_in[p++];
    const float* w_norm1  = (const float*)d_in[p++];
    const float* wq       = (const float*)d_in[p++];
    const float* wk       = (const float*)d_in[p++];
    const float* wv       = (const float*)d_in[p++];
    const float* wo       = (const float*)d_in[p++];
    const float* w_norm2  = (const float*)d_in[p++];
    const float* w1       = (const float*)d_in[p++];
    const float* w3       = (const float*)d_in[p++];
    const float* w2       = (const float*)d_in[p++];
    const float* w_metric = (const float*)d_in[p++];
    float* out = (float*)d_out;

    float *gx1, *gh, *gq, *gk, *gv, *gf1, *gf2, *gm;
    cudaGetSymbolAddress((void**)&gx1, g_x1);
    cudaGetSymbolAddress((void**)&gh,  g_h);
    cudaGetSymbolAddress((void**)&gq,  g_q);
    cudaGetSymbolAddress((void**)&gk,  g_k);
    cudaGetSymbolAddress((void**)&gv,  g_v);
    cudaGetSymbolAddress((void**)&gf1, g_f1);
    cudaGetSymbolAddress((void**)&gf2, g_f2);
    cudaGetSymbolAddress((void**)&gm,  g_metric);

    span_add_kernel<<<TT, 256>>>(x, span, w_span);
    rms_kernel<<<TT, 256>>>(gx1, w_norm1, gh);
    sgemm128_kernel<0><<<dim3(DD / 128, TT / 128), 256>>>(gh, wq, nullptr, gq, TT, DD, DD);
    sgemm128_kernel<0><<<dim3(DD / 128, TT / 128), 256>>>(gh, wk, nullptr, gk, TT, DD, DD);
    sgemm128_kernel<0><<<dim3(DD / 128, TT / 128), 256>>>(gh, wv, nullptr, gv, TT, DD, DD);
    rope_kernel<<<TT, 512>>>(gq, gk, pos, freqs);
    attn_kernel<<<BB * NWIN * HH, 256>>>(gq, gk, gv);
    sgemm128_kernel<1><<<dim3(DD / 128, TT / 128), 256>>>(gq, wo, gx1, gx1, TT, DD, DD);
    rms_kernel<<<TT, 256>>>(gx1, w_norm2, gh);
    sgemm128_kernel<0><<<dim3(FFD / 128, TT / 128), 256>>>(gh, w1, nullptr, gf1, TT, FFD, DD);
    sgemm128_kernel<0><<<dim3(FFD / 128, TT / 128), 256>>>(gh, w3, nullptr, gf2, TT, FFD, DD);
    silu_mul_kernel<<<(int)(((size_t)TT * FFD / 4) / 256), 256>>>();
    sgemm128_kernel<1><<<dim3(DD / 128, TT / 128), 256>>>(gf1, w2, gx1, gx1, TT, DD, FFD);
    sgemm64_kernel<<<dim3(GMD / 64, TT / 64), dim3(16, 16)>>>(gx1, w_metric, gm, TT, GMD, DD);
    norm_metric_kernel<<<TT, 32>>>();
    real_kernel<<<BB * SS, 256>>>(source, pad_mask);
    sim_kernel<<<BB * PP, 32>>>();
    topk_kernel<<<BB, 1024>>>();
    gather_kernel<<<dim3(SS, BB), 256>>>(source, pos, span, out);

    (void)out_size; (void)n_in;
}

// round 5
// speedup vs baseline: 2.3748x; 2.3748x over previous
#include <cuda_runtime.h>
#include <cuda_fp16.h>
#include <math.h>
#include <stdint.h>

// ---------------- problem constants ----------------
#define BB   4
#define SS   2048
#define DD   1024
#define HH   16
#define DHH  64
#define FFD  4096
#define WINW 16
#define GMD  64
#define RR   512
#define NWIN (SS / WINW)          // 128
#define TT   (BB * SS)            // 8192 tokens
#define PP   (SS / 2)             // 1024 pairs per batch
#define KEEPN (SS - RR)           // 1536 kept per batch

// output offsets (float32 concatenation of the 4 outputs)
#define X_OUT_OFF   ((size_t)0)
#define SRC_OUT_OFF ((size_t)BB * KEEPN * DD)
#define POS_OUT_OFF (SRC_OUT_OFF + (size_t)BB * KEEPN * SS)
#define SP_OUT_OFF  (POS_OUT_OFF + (size_t)BB * KEEPN)

// ---------------- scratch (static device buffers; no allocation) --------------
__device__ float g_x1[(size_t)TT * DD];
__device__ float g_h [(size_t)TT * DD];
__device__ float g_q [(size_t)TT * DD];
__device__ float g_k [(size_t)TT * DD];
__device__ float g_v [(size_t)TT * DD];
__device__ float g_f1[(size_t)TT * FFD];
__device__ float g_f2[(size_t)TT * FFD];
__device__ float g_metric[(size_t)TT * GMD];
__device__ float g_sim [BB * PP];
__device__ int   g_flag[BB * PP];
__device__ int   g_pf  [BB * PP];
__device__ int   g_real[BB * SS];

// fp16 hi/lo split activations (A matrices), reused across GEMMs
__device__ __half g_ah[(size_t)TT * FFD];
__device__ __half g_al[(size_t)TT * FFD];

// transposed fp16 hi/lo weights: Wt[n][k]
__device__ __half g_wqh[DD * DD],  g_wql[DD * DD];
__device__ __half g_wkh[DD * DD],  g_wkl[DD * DD];
__device__ __half g_wvh[DD * DD],  g_wvl[DD * DD];
__device__ __half g_woh[DD * DD],  g_wol[DD * DD];
__device__ __half g_w1h[(size_t)FFD * DD], g_w1l[(size_t)FFD * DD];
__device__ __half g_w3h[(size_t)FFD * DD], g_w3l[(size_t)FFD * DD];
__device__ __half g_w2h[(size_t)DD * FFD], g_w2l[(size_t)DD * FFD];

// ---------------- helpers ----------------
__device__ __forceinline__ uint32_t smem_u32(const void* p) {
    uint32_t a;
    asm("{ .reg .u64 t; cvta.to.shared.u64 t, %1; cvt.u32.u64 %0, t; }" : "=r"(a) : "l"(p));
    return a;
}
__device__ __forceinline__ uint32_t pkh(__half a, __half b) {
    __half2 t; t.x = a; t.y = b;
    return *(uint32_t*)&t;
}

#define MMA16816(d, a, b0v, b1v)                                                      \
    asm volatile("mma.sync.aligned.m16n8k16.row.col.f32.f16.f16.f32 "                 \
        "{%0,%1,%2,%3}, {%4,%5,%6,%7}, {%8,%9}, {%0,%1,%2,%3};"                       \
        : "+f"((d)[0]), "+f"((d)[1]), "+f"((d)[2]), "+f"((d)[3])                      \
        : "r"((a)[0]), "r"((a)[1]), "r"((a)[2]), "r"((a)[3]), "r"(b0v), "r"(b1v))

#define LDSM4(r, addr)                                                                \
    asm volatile("ldmatrix.sync.aligned.m8n8.x4.shared.b16 {%0,%1,%2,%3}, [%4];"      \
        : "=r"((r)[0]), "=r"((r)[1]), "=r"((r)[2]), "=r"((r)[3]) : "r"(addr))

#define CP16(dst, src)                                                                \
    asm volatile("cp.async.cg.shared.global [%0], [%1], 16;" :: "r"(dst), "l"(src))
#define CP_COMMIT() asm volatile("cp.async.commit_group;")
#define CP_WAIT1()  asm volatile("cp.async.wait_group 1;")
#define CP_WAIT0()  asm volatile("cp.async.wait_group 0;")

// ---------------- weight transpose + fp16 hi/lo split ----------------
// out: T[n][k] = split(W[k][n]),   W is [K,N] row-major
__global__ void wconv_kernel(const float* __restrict__ W, __half* __restrict__ Th,
                             __half* __restrict__ Tl, int K, int N) {
    __shared__ float t[32][33];
    int n0 = blockIdx.x * 32, k0 = blockIdx.y * 32;
    int tx = threadIdx.x, ty = threadIdx.y;     // (32, 8)
#pragma unroll
    for (int i = 0; i < 4; i++)
        t[ty + i * 8][tx] = W[(size_t)(k0 + ty + i * 8) * N + n0 + tx];
    __syncthreads();
#pragma unroll
    for (int i = 0; i < 4; i++) {
        int n = n0 + ty + i * 8, k = k0 + tx;
        float v = t[tx][ty + i * 8];
        __half h = __float2half_rn(v);
        __half l = __float2half_rn(v - __half2float(h));
        Th[(size_t)n * K + k] = h;
        Tl[(size_t)n * K + k] = l;
    }
}

// ---------------- activation fp32 -> fp16 hi/lo split ----------------
__global__ void a2h_kernel(const float* __restrict__ A, int n4) {
    int i = blockIdx.x * 256 + threadIdx.x;
    if (i >= n4) return;
    float4 a = ((const float4*)A)[i];
    __half h0 = __float2half_rn(a.x), h1 = __float2half_rn(a.y);
    __half h2 = __float2half_rn(a.z), h3 = __float2half_rn(a.w);
    __half l0 = __float2half_rn(a.x - __half2float(h0));
    __half l1 = __float2half_rn(a.y - __half2float(h1));
    __half l2 = __float2half_rn(a.z - __half2float(h2));
    __half l3 = __float2half_rn(a.w - __half2float(h3));
    ((uint2*)g_ah)[i] = make_uint2(pkh(h0, h1), pkh(h2, h3));
    ((uint2*)g_al)[i] = make_uint2(pkh(l0, l1), pkh(l2, l3));
}

// ---------------- fp16x3 tensor-core GEMM ----------------
// C[M,N](+Rs) = A[M,K] @ Wt[N,K]^T with A,W split hi/lo fp16.
// Tile 256x128, Kc=32, 256 threads (8 warps, 64x64 warp tiles), cp.async x2 buf.
#define TBM 256
#define TBN 128
#define TKC 32
#define ROWP 80                         // padded row bytes (40 halves)
#define AH_OFF 0
#define AL_OFF (TBM * ROWP)             // 20480
#define WH_OFF (2 * TBM * ROWP)         // 40960
#define WL_OFF (WH_OFF + TBN * ROWP)    // 51200
#define BUF_SZ (WL_OFF + TBN * ROWP)    // 61440
#define SMEM_G (2 * BUF_SZ)             // 122880

template <int KTOT, int ADD>
__global__ void __launch_bounds__(256, 1)
hgemm_kernel(const __half* __restrict__ Ah, const __half* __restrict__ Al,
             const __half* __restrict__ Wh, const __half* __restrict__ Wl,
             const float* __restrict__ Rs, float* __restrict__ C, int N) {
    extern __shared__ char smem[];
    const uint32_t sb = smem_u32(smem);
    const int tid = threadIdx.x, wid = tid >> 5, lane = tid & 31;
    const int wm = wid & 3, wn = wid >> 2;
    const int bm = blockIdx.y * TBM, bn = blockIdx.x * TBN;

    float acc[4][8][4];
#pragma unroll
    for (int i = 0; i < 4; i++)
#pragma unroll
        for (int j = 0; j < 8; j++)
#pragma unroll
            for (int k = 0; k < 4; k++) acc[i][j][k] = 0.f;

    // ldmatrix per-lane addressing
    const int a_row = lane & 15;
    const int a_k8 = (lane >> 4) << 3;               // 0 or 8
    const int b_row = (lane & 7) | ((lane >> 4) << 3);
    const int b_k8 = ((lane >> 3) & 1) << 3;

    auto load_chunk = [&](int c, int p) {
        uint32_t base = sb + p * BUF_SZ;
        size_t kof = (size_t)c * TKC;
#pragma unroll
        for (int i = 0; i < 4; i++) {                // A: 1024 x 16B (hi) + (lo)
            int lin = tid + i * 256;
            int r = lin >> 2, q = lin & 3;
            size_t g = (size_t)(bm + r) * KTOT + kof + q * 8;
            uint32_t d = base + AH_OFF + r * ROWP + q * 16;
            CP16(d, Ah + g);
            CP16(d + (AL_OFF - AH_OFF), Al + g);
        }
#pragma unroll
        for (int i = 0; i < 2; i++) {                // W: 512 x 16B (hi) + (lo)
            int lin = tid + i * 256;
            int r = lin >> 2, q = lin & 3;
            size_t g = (size_t)(bn + r) * KTOT + kof + q * 8;
            uint32_t d = base + WH_OFF + r * ROWP + q * 16;
            CP16(d, Wh + g);
            CP16(d + (WL_OFF - WH_OFF), Wl + g);
        }
    };

    auto compute = [&](int p) {
        uint32_t base = sb + p * BUF_SZ;
#pragma unroll
        for (int ks = 0; ks < 2; ks++) {
            uint32_t aH[4][4], aL[4][4];
#pragma unroll
            for (int mt = 0; mt < 4; mt++) {
                uint32_t ra = base + AH_OFF + (wm * 64 + mt * 16 + a_row) * ROWP
                            + (ks * 16 + a_k8) * 2;
                LDSM4(aH[mt], ra);
                LDSM4(aL[mt], ra + (AL_OFF - AH_OFF));
            }
#pragma unroll
            for (int ng = 0; ng < 4; ng++) {
                uint32_t bH[4], bL[4];
                uint32_t rb = base + WH_OFF + (wn * 64 + ng * 16 + b_row) * ROWP
                            + (ks * 16 + b_k8) * 2;
                LDSM4(bH, rb);
                LDSM4(bL, rb + (WL_OFF - WH_OFF));
#pragma unroll
                for (int mt = 0; mt < 4; mt++) {
#pragma unroll
                    for (int j = 0; j < 2; j++) {
                        float* d = acc[mt][ng * 2 + j];
                        MMA16816(d, aH[mt], bH[2 * j], bH[2 * j + 1]);
                        MMA16816(d, aL[mt], bH[2 * j], bH[2 * j + 1]);
                        MMA16816(d, aH[mt], bL[2 * j], bL[2 * j + 1]);
                    }
                }
            }
        }
    };

    constexpr int NCH = KTOT / TKC;
    load_chunk(0, 0);
    CP_COMMIT();
    for (int c = 0; c < NCH; c++) {
        if (c + 1 < NCH) {
            load_chunk(c + 1, (c + 1) & 1);
            CP_COMMIT();
            CP_WAIT1();
        } else {
            CP_WAIT0();
        }
        __syncthreads();
        compute(c & 1);
        __syncthreads();
    }

    // epilogue
    const int mrow = lane >> 2, ncol = (lane & 3) * 2;
#pragma unroll
    for (int mt = 0; mt < 4; mt++) {
        int m0 = bm + wm * 64 + mt * 16 + mrow;
#pragma unroll
        for (int n8 = 0; n8 < 8; n8++) {
            int n0 = bn + wn * 64 + n8 * 8 + ncol;
            float* d = acc[mt][n8];
            float2 v0 = make_float2(d[0], d[1]);
            float2 v1 = make_float2(d[2], d[3]);
            if (ADD) {
                float2 r0 = *(const float2*)(Rs + (size_t)m0 * N + n0);
                float2 r1 = *(const float2*)(Rs + (size_t)(m0 + 8) * N + n0);
                v0.x += r0.x; v0.y += r0.y; v1.x += r1.x; v1.y += r1.y;
            }
            *(float2*)(C + (size_t)m0 * N + n0) = v0;
            *(float2*)(C + (size_t)(m0 + 8) * N + n0) = v1;
        }
    }
}

// ---------------- elementwise / norm kernels ----------------
__global__ void span_add_kernel(const float* __restrict__ x, const int* __restrict__ span,
                                const float* __restrict__ w_span) {
    int row = blockIdx.x;
    float se = log1pf((float)span[row]);
    const float4* xr = (const float4*)(x + (size_t)row * DD);
    const float4* wr = (const float4*)w_span;
    float4* o = (float4*)(g_x1 + (size_t)row * DD);
    int t = threadIdx.x;
    float4 a = xr[t], w = wr[t];
    o[t] = make_float4(a.x + se * w.x, a.y + se * w.y, a.z + se * w.z, a.w + se * w.w);
}

__global__ void rms_kernel(const float* __restrict__ x, const float* __restrict__ w,
                           float* __restrict__ out) {
    int row = blockIdx.x;
    const float4* xr = (const float4*)(x + (size_t)row * DD);
    int t = threadIdx.x;
    float4 a = xr[t];
    float ss = a.x * a.x + a.y * a.y + a.z * a.z + a.w * a.w;
    for (int off = 16; off > 0; off >>= 1) ss += __shfl_xor_sync(0xffffffffu, ss, off);
    __shared__ float red[8];
    if ((t & 31) == 0) red[t >> 5] = ss;
    __syncthreads();
    if (t < 8) {
        float v = red[t];
        for (int off = 4; off > 0; off >>= 1) v += __shfl_xor_sync(0xffu, v, off);
        if (t == 0) red[0] = v;
    }
    __syncthreads();
    float scale = rsqrtf(red[0] / (float)DD + 1e-6f);
    const float4* wr = (const float4*)w;
    float4 wv = wr[t];
    float4* o = (float4*)(out + (size_t)row * DD);
    o[t] = make_float4(a.x * scale * wv.x, a.y * scale * wv.y,
                       a.z * scale * wv.z, a.w * scale * wv.w);
}

// ---------------- SGEMM 64x64 fp32 (metric GEMM, N=64) ----------------
__global__ void sgemm64_kernel(const float* __restrict__ A, const float* __restrict__ W,
                               float* __restrict__ C, int M, int N, int K) {
    __shared__ float As[16][68];
    __shared__ float Ws[16][68];
    int tx = threadIdx.x, ty = threadIdx.y;
    int tid = ty * 16 + tx;
    int bm = blockIdx.y * 64, bn = blockIdx.x * 64;
    float acc[4][4] = {};
    for (int k0 = 0; k0 < K; k0 += 16) {
        {
            int r = tid >> 2, c = (tid & 3) * 4;
            float4 a = *(const float4*)(A + (size_t)(bm + r) * K + k0 + c);
            As[c + 0][r] = a.x; As[c + 1][r] = a.y; As[c + 2][r] = a.z; As[c + 3][r] = a.w;
        }
        {
            int r = tid >> 4, c = (tid & 15) * 4;
            *(float4*)(&Ws[r][c]) = *(const float4*)(W + (size_t)(k0 + r) * N + bn + c);
        }
        __syncthreads();
#pragma unroll
        for (int kk = 0; kk < 16; kk++) {
            float4 a = *(const float4*)(&As[kk][ty * 4]);
            float4 b = *(const float4*)(&Ws[kk][tx * 4]);
            float av[4] = {a.x, a.y, a.z, a.w};
            float bw[4] = {b.x, b.y, b.z, b.w};
#pragma unroll
            for (int i = 0; i < 4; i++)
#pragma unroll
                for (int j = 0; j < 4; j++) acc[i][j] += av[i] * bw[j];
        }
        __syncthreads();
    }
#pragma unroll
    for (int i = 0; i < 4; i++) {
        int m = bm + ty * 4 + i;
#pragma unroll
        for (int j = 0; j < 4; j++) C[(size_t)m * N + bn + tx * 4 + j] = acc[i][j];
    }
}

// ---------------- RoPE (in place on q and k) ----------------
__global__ void rope_kernel(float* __restrict__ q, float* __restrict__ k,
                            const int* __restrict__ pos, const float* __restrict__ freqs) {
    int row = blockIdx.x;
    int t = threadIdx.x;                  // 512 = 16 heads * 32 pairs
    int h = t >> 5, dp = t & 31;
    float ang = (float)pos[row] * freqs[dp];
    float c = cosf(ang), s = sinf(ang);
    size_t base = (size_t)row * DD + h * DHH + dp;
    float a = q[base], b = q[base + 32];
    q[base] = a * c - b * s; q[base + 32] = a * s + b * c;
    a = k[base]; b = k[base + 32];
    k[base] = a * c - b * s; k[base + 32] = a * s + b * c;
}

// ---------------- windowed attention; writes o in-place into q ----------------
__global__ void attn_kernel(float* __restrict__ q, const float* __restrict__ k,
                            const float* __restrict__ v) {
    int blk = blockIdx.x;
    int head = blk % HH;
    int win = (blk / HH) % NWIN;
    int b = blk / (HH * NWIN);
    int s0 = b * SS + win * WINW;

    __shared__ float sq[16][68], sk[16][68], sv[16][68], sp[16][17];
    int tid = threadIdx.x;                // 256
    {
        int r = tid >> 4, c = (tid & 15) * 4;
        size_t g = (size_t)(s0 + r) * DD + head * DHH + c;
        *(float4*)(&sq[r][c]) = *(const float4*)(q + g);
        *(float4*)(&sk[r][c]) = *(const float4*)(k + g);
        *(float4*)(&sv[r][c]) = *(const float4*)(v + g);
    }
    __syncthreads();

    int qi = tid >> 4, ki = tid & 15;
    float sc = 0.f;
#pragma unroll
    for (int d = 0; d < DHH; d++) sc += sq[qi][d] * sk[ki][d];
    sc *= 0.125f;
    float m = sc;
#pragma unroll
    for (int off = 8; off > 0; off >>= 1) m = fmaxf(m, __shfl_xor_sync(0xffffffffu, m, off, 16));
    float e = expf(sc - m);
    float su = e;
#pragma unroll
    for (int off = 8; off > 0; off >>= 1) su += __shfl_xor_sync(0xffffffffu, su, off, 16);
    sp[qi][ki] = e / su;
    __syncthreads();

    int dg = tid & 15;
    float4 acc = make_float4(0.f, 0.f, 0.f, 0.f);
#pragma unroll
    for (int kk = 0; kk < 16; kk++) {
        float p = sp[qi][kk];
        acc.x += p * sv[kk][dg * 4 + 0];
        acc.y += p * sv[kk][dg * 4 + 1];
        acc.z += p * sv[kk][dg * 4 + 2];
        acc.w += p * sv[kk][dg * 4 + 3];
    }
    size_t go = (size_t)(s0 + qi) * DD + head * DHH + dg * 4;
    *(float4*)(q + go) = acc;
}

// ---------------- silu(f1)*f2 -> f1 ----------------
__global__ void silu_mul_kernel() {
    size_t i = ((size_t)blockIdx.x * blockDim.x + threadIdx.x);
    float4 a = ((const float4*)g_f1)[i];
    float4 b = ((const float4*)g_f2)[i];
    a.x = a.x / (1.f + expf(-a.x)) * b.x;
    a.y = a.y / (1.f + expf(-a.y)) * b.y;
    a.z = a.z / (1.f + expf(-a.z)) * b.z;
    a.w = a.w / (1.f + expf(-a.w)) * b.w;
    ((float4*)g_f1)[i] = a;
}

// ---------------- metric normalization ----------------
__global__ void norm_metric_kernel() {
    int row = blockIdx.x;
    int t = threadIdx.x;                  // 32
    float* mr = g_metric + (size_t)row * GMD;
    float a = mr[t], b = mr[t + 32];
    float ss = a * a + b * b;
#pragma unroll
    for (int off = 16; off > 0; off >>= 1) ss += __shfl_xor_sync(0xffffffffu, ss, off);
    float inv = 1.f / (sqrtf(ss) + 1e-6f);
    mr[t] = a * inv; mr[t + 32] = b * inv;
}

// ---------------- real[b,s] = sum_j source[b,s,j]*pad[b,j] > 0 ----------------
__global__ void real_kernel(const float* __restrict__ source, const float* __restrict__ pad) {
    int row = blockIdx.x;
    int b = row / SS;
    const float* sr = source + (size_t)row * SS;
    const float* pr = pad + (size_t)b * SS;
    float su = 0.f;
    for (int j = threadIdx.x; j < SS; j += 256) su += sr[j] * pr[j];
    for (int off = 16; off > 0; off >>= 1) su += __shfl_xor_sync(0xffffffffu, su, off);
    __shared__ float red[8];
    if ((threadIdx.x & 31) == 0) red[threadIdx.x >> 5] = su;
    __syncthreads();
    if (threadIdx.x == 0) {
        float tot = 0.f;
        for (int i = 0; i < 8; i++) tot += red[i];
        g_real[row] = (tot > 0.f) ? 1 : 0;
    }
}

// ---------------- sim[b,p] ----------------
__global__ void sim_kernel() {
    int bp = blockIdx.x;
    int b = bp / PP, p = bp % PP;
    int t = threadIdx.x;                  // 32
    const float* me = g_metric + ((size_t)b * SS + 2 * p) * GMD;
    const float* mo = me + GMD;
    float d = me[t] * mo[t] + me[t + 32] * mo[t + 32];
#pragma unroll
    for (int off = 16; off > 0; off >>= 1) d += __shfl_xor_sync(0xffffffffu, d, off);
    if (t == 0) {
        int ok = g_real[b * SS + 2 * p] & g_real[b * SS + 2 * p + 1];
        g_sim[bp] = ok ? d : -10000.0f;
    }
}

// ---------------- per-batch top-k(512): bitonic sort + flags + prefix scan ----
__global__ void topk_kernel() {
    int b = blockIdx.x;
    int tid = threadIdx.x;                // 1024
    __shared__ float val[1024];
    __shared__ int idx[1024];
    __shared__ int sf[1024];
    __shared__ int sc[1024];
    val[tid] = g_sim[b * PP + tid];
    idx[tid] = tid;
    __syncthreads();
    for (int k = 2; k <= 1024; k <<= 1) {
        for (int j = k >> 1; j > 0; j >>= 1) {
            int ixj = tid ^ j;
            if (ixj > tid) {
                bool dirDesc = ((tid & k) == 0);
                float v1 = val[tid], v2 = val[ixj];
                int i1 = idx[tid], i2 = idx[ixj];
                bool firstHigher = (v1 > v2) || (v1 == v2 && i1 < i2);
                if (dirDesc ? !firstHigher : firstHigher) {
                    val[tid] = v2; val[ixj] = v1;
                    idx[tid] = i2; idx[ixj] = i1;
                }
            }
            __syncthreads();
        }
    }
    sf[tid] = 0;
    __syncthreads();
    if (tid < RR) sf[idx[tid]] = 1;
    __syncthreads();
    int f = sf[tid];
    g_flag[b * PP + tid] = f;
    sc[tid] = f;
    __syncthreads();
    for (int off = 1; off < 1024; off <<= 1) {
        int t = (tid >= off) ? sc[tid - off] : 0;
        __syncthreads();
        sc[tid] += t;
        __syncthreads();
    }
    g_pf[b * PP + tid] = sc[tid] - f;
}

// ---------------- merge + compact + gather all 4 outputs ----------------
__global__ void gather_kernel(const float* __restrict__ source, const int* __restrict__ pos,
                              const int* __restrict__ span, float* __restrict__ out) {
    int b = blockIdx.y, s = blockIdx.x;
    int p = s >> 1;
    int f = g_flag[b * PP + p];
    bool odd = s & 1;
    if (odd && f) return;
    int j = s - g_pf[b * PP + p];
    int tid = threadIdx.x;                // 256

    const float* xr = g_x1 + ((size_t)b * SS + s) * DD;
    float* xo = out + X_OUT_OFF + ((size_t)b * KEEPN + j) * DD;
    if (!odd && f) {
        float sze = (float)span[b * SS + s];
        float szo = (float)span[b * SS + s + 1];
        float inv = 1.f / (sze + szo);
        const float* xr2 = xr + DD;
        for (int d = tid; d < DD; d += 256) xo[d] = (sze * xr[d] + szo * xr2[d]) * inv;
    } else {
        for (int d = tid; d < DD; d += 256) xo[d] = xr[d];
    }
    const float* sr = source + ((size_t)b * SS + s) * SS;
    float* so = out + SRC_OUT_OFF + ((size_t)b * KEEPN + j) * SS;
    if (!odd && f) {
        const float* sr2 = sr + SS;
        for (int t = tid; t < SS; t += 256) so[t] = sr[t] + sr2[t];
    } else {
        for (int t = tid; t < SS; t += 256) so[t] = sr[t];
    }
    if (tid == 0) {
        out[POS_OUT_OFF + (size_t)b * KEEPN + j] = (float)pos[b * SS + s];
        int sp = span[b * SS + s];
        if (!odd && f) sp += span[b * SS + s + 1];
        out[SP_OUT_OFF + (size_t)b * KEEPN + j] = (float)sp;
    }
}

// ---------------- launch ----------------
extern "C" void kernel_launch(void* const* d_in, const int* in_sizes, int n_in,
                              void* d_out, int out_size) {
    int p = 0;
    const float* x        = (const float*)d_in[p++];
    const float* source   = (const float*)d_in[p++];
    const int*   pos      = (const int*)  d_in[p++];
    const int*   span     = (const int*)  d_in[p++];
    if (p < n_in && in_sizes[p] == 1) p++;            // scalar r, if passed
    const float* freqs    = (const float*)d_in[p++];
    const float* pad_mask = (const float*)d_in[p++];
    p++;                                               // seq_pad_mask (all true; unused)
    const float* w_span   = (const float*)d_in[p++];
    const float* w_norm1  = (const float*)d_in[p++];
    const float* wq       = (const float*)d_in[p++];
    const float* wk       = (const float*)d_in[p++];
    const float* wv       = (const float*)d_in[p++];
    const float* wo       = (const float*)d_in[p++];
    const float* w_norm2  = (const float*)d_in[p++];
    const float* w1       = (const float*)d_in[p++];
    const float* w3       = (const float*)d_in[p++];
    const float* w2       = (const float*)d_in[p++];
    const float* w_metric = (const float*)d_in[p++];
    float* out = (float*)d_out;

    float *gx1, *gh, *gq, *gk, *gv, *gf1, *gf2, *gm;
    cudaGetSymbolAddress((void**)&gx1, g_x1);
    cudaGetSymbolAddress((void**)&gh,  g_h);
    cudaGetSymbolAddress((void**)&gq,  g_q);
    cudaGetSymbolAddress((void**)&gk,  g_k);
    cudaGetSymbolAddress((void**)&gv,  g_v);
    cudaGetSymbolAddress((void**)&gf1, g_f1);
    cudaGetSymbolAddress((void**)&gf2, g_f2);
    cudaGetSymbolAddress((void**)&gm,  g_metric);

    __half *gah, *gal;
    cudaGetSymbolAddress((void**)&gah, g_ah);
    cudaGetSymbolAddress((void**)&gal, g_al);

    __half *wqh, *wql, *wkh, *wkl, *wvh, *wvl, *woh, *wol;
    __half *w1h, *w1l, *w3h, *w3l, *w2h, *w2l;
    cudaGetSymbolAddress((void**)&wqh, g_wqh); cudaGetSymbolAddress((void**)&wql, g_wql);
    cudaGetSymbolAddress((void**)&wkh, g_wkh); cudaGetSymbolAddress((void**)&wkl, g_wkl);
    cudaGetSymbolAddress((void**)&wvh, g_wvh); cudaGetSymbolAddress((void**)&wvl, g_wvl);
    cudaGetSymbolAddress((void**)&woh, g_woh); cudaGetSymbolAddress((void**)&wol, g_wol);
    cudaGetSymbolAddress((void**)&w1h, g_w1h); cudaGetSymbolAddress((void**)&w1l, g_w1l);
    cudaGetSymbolAddress((void**)&w3h, g_w3h); cudaGetSymbolAddress((void**)&w3l, g_w3l);
    cudaGetSymbolAddress((void**)&w2h, g_w2h); cudaGetSymbolAddress((void**)&w2l, g_w2l);

    cudaFuncSetAttribute(hgemm_kernel<1024, 0>, cudaFuncAttributeMaxDynamicSharedMemorySize, SMEM_G);
    cudaFuncSetAttribute(hgemm_kernel<1024, 1>, cudaFuncAttributeMaxDynamicSharedMemorySize, SMEM_G);
    cudaFuncSetAttribute(hgemm_kernel<4096, 1>, cudaFuncAttributeMaxDynamicSharedMemorySize, SMEM_G);

    dim3 wcb(32, 8);
    wconv_kernel<<<dim3(DD / 32, DD / 32), wcb>>>(wq, wqh, wql, DD, DD);
    wconv_kernel<<<dim3(DD / 32, DD / 32), wcb>>>(wk, wkh, wkl, DD, DD);
    wconv_kernel<<<dim3(DD / 32, DD / 32), wcb>>>(wv, wvh, wvl, DD, DD);
    wconv_kernel<<<dim3(DD / 32, DD / 32), wcb>>>(wo, woh, wol, DD, DD);
    wconv_kernel<<<dim3(FFD / 32, DD / 32), wcb>>>(w1, w1h, w1l, DD, FFD);
    wconv_kernel<<<dim3(FFD / 32, DD / 32), wcb>>>(w3, w3h, w3l, DD, FFD);
    wconv_kernel<<<dim3(DD / 32, FFD / 32), wcb>>>(w2, w2h, w2l, FFD, DD);

    const int nD4 = TT * DD / 4;             // 2M
    const int nF4 = TT * FFD / 4;            // 8M
    dim3 gQ(DD / TBN, TT / TBM);             // (8, 32)
    dim3 gF(FFD / TBN, TT / TBM);            // (32, 32)

    span_add_kernel<<<TT, 256>>>(x, span, w_span);
    rms_kernel<<<TT, 256>>>(gx1, w_norm1, gh);
    a2h_kernel<<<(nD4 + 255) / 256, 256>>>(gh, nD4);
    hgemm_kernel<1024, 0><<<gQ, 256, SMEM_G>>>(gah, gal, wqh, wql, nullptr, gq, DD);
    hgemm_kernel<1024, 0><<<gQ, 256, SMEM_G>>>(gah, gal, wkh, wkl, nullptr, gk, DD);
    hgemm_kernel<1024, 0><<<gQ, 256, SMEM_G>>>(gah, gal, wvh, wvl, nullptr, gv, DD);
    rope_kernel<<<TT, 512>>>(gq, gk, pos, freqs);
    attn_kernel<<<BB * NWIN * HH, 256>>>(gq, gk, gv);
    a2h_kernel<<<(nD4 + 255) / 256, 256>>>(gq, nD4);
    hgemm_kernel<1024, 1><<<gQ, 256, SMEM_G>>>(gah, gal, woh, wol, gx1, gx1, DD);
    rms_kernel<<<TT, 256>>>(gx1, w_norm2, gh);
    a2h_kernel<<<(nD4 + 255) / 256, 256>>>(gh, nD4);
    hgemm_kernel<1024, 0><<<gF, 256, SMEM_G>>>(gah, gal, w1h, w1l, nullptr, gf1, FFD);
    hgemm_kernel<1024, 0><<<gF, 256, SMEM_G>>>(gah, gal, w3h, w3l, nullptr, gf2, FFD);
    silu_mul_kernel<<<nF4 / 256, 256>>>();
    a2h_kernel<<<(nF4 + 255) / 256, 256>>>(gf1, nF4);
    hgemm_kernel<4096, 1><<<gQ, 256, SMEM_G>>>(gah, gal, w2h, w2l, gx1, gx1, DD);
    sgemm64_kernel<<<dim3(GMD / 64, TT / 64), dim3(16, 16)>>>(gx1, w_metric, gm, TT, GMD, DD);
    norm_metric_kernel<<<TT, 32>>>();
    real_kernel<<<BB * SS, 256>>>(source, pad_mask);
    sim_kernel<<<BB * PP, 32>>>();
    topk_kernel<<<BB, 1024>>>();
    gather_kernel<<<dim3(SS, BB), 256>>>(source, pos, span, out);

    (void)out_size; (void)n_in;
}

// round 6
// speedup vs baseline: 2.4697x; 1.0400x over previous
#include <cuda_runtime.h>
#include <cuda_fp16.h>
#include <math.h>
#include <stdint.h>

// ---------------- problem constants ----------------
#define BB   4
#define SS   2048
#define DD   1024
#define HH   16
#define DHH  64
#define FFD  4096
#define WINW 16
#define GMD  64
#define RR   512
#define NWIN (SS / WINW)          // 128
#define TT   (BB * SS)            // 8192 tokens
#define PP   (SS / 2)             // 1024 pairs per batch
#define KEEPN (SS - RR)           // 1536 kept per batch

// output offsets (float32 concatenation of the 4 outputs)
#define X_OUT_OFF   ((size_t)0)
#define SRC_OUT_OFF ((size_t)BB * KEEPN * DD)
#define POS_OUT_OFF (SRC_OUT_OFF + (size_t)BB * KEEPN * SS)
#define SP_OUT_OFF  (POS_OUT_OFF + (size_t)BB * KEEPN)

// ---------------- scratch (static device buffers; no allocation) --------------
__device__ float g_x1[(size_t)TT * DD];
__device__ float g_q [(size_t)TT * DD];
__device__ float g_k [(size_t)TT * DD];
__device__ float g_v [(size_t)TT * DD];
__device__ float g_f1[(size_t)TT * FFD];
__device__ float g_f2[(size_t)TT * FFD];
__device__ float g_metric[(size_t)TT * GMD];
__device__ float g_sim [BB * PP];
__device__ int   g_flag[BB * PP];
__device__ int   g_pf  [BB * PP];
__device__ int   g_real[BB * SS];

// fp16 hi/lo split activations (A matrices), reused across GEMMs
__device__ __half g_ah[(size_t)TT * FFD];
__device__ __half g_al[(size_t)TT * FFD];

// transposed fp16 hi/lo weights: Wt[n][k]
__device__ __half g_wqh[DD * DD],  g_wql[DD * DD];
__device__ __half g_wkh[DD * DD],  g_wkl[DD * DD];
__device__ __half g_wvh[DD * DD],  g_wvl[DD * DD];
__device__ __half g_woh[DD * DD],  g_wol[DD * DD];
__device__ __half g_w1h[(size_t)FFD * DD], g_w1l[(size_t)FFD * DD];
__device__ __half g_w3h[(size_t)FFD * DD], g_w3l[(size_t)FFD * DD];
__device__ __half g_w2h[(size_t)DD * FFD], g_w2l[(size_t)DD * FFD];

// ---------------- helpers ----------------
__device__ __forceinline__ uint32_t smem_u32(const void* p) {
    uint32_t a;
    asm("{ .reg .u64 t; cvta.to.shared.u64 t, %1; cvt.u32.u64 %0, t; }" : "=r"(a) : "l"(p));
    return a;
}
__device__ __forceinline__ uint32_t pkh(__half a, __half b) {
    __half2 t; t.x = a; t.y = b;
    return *(uint32_t*)&t;
}
// split one fp32 into hi/lo fp16 pair packed per 4-float group
__device__ __forceinline__ void split4(float4 a, uint2& hi, uint2& lo) {
    __half h0 = __float2half_rn(a.x), h1 = __float2half_rn(a.y);
    __half h2 = __float2half_rn(a.z), h3 = __float2half_rn(a.w);
    __half l0 = __float2half_rn(a.x - __half2float(h0));
    __half l1 = __float2half_rn(a.y - __half2float(h1));
    __half l2 = __float2half_rn(a.z - __half2float(h2));
    __half l3 = __float2half_rn(a.w - __half2float(h3));
    hi = make_uint2(pkh(h0, h1), pkh(h2, h3));
    lo = make_uint2(pkh(l0, l1), pkh(l2, l3));
}

#define MMA16816(d, a, b0v, b1v)                                                      \
    asm volatile("mma.sync.aligned.m16n8k16.row.col.f32.f16.f16.f32 "                 \
        "{%0,%1,%2,%3}, {%4,%5,%6,%7}, {%8,%9}, {%0,%1,%2,%3};"                       \
        : "+f"((d)[0]), "+f"((d)[1]), "+f"((d)[2]), "+f"((d)[3])                      \
        : "r"((a)[0]), "r"((a)[1]), "r"((a)[2]), "r"((a)[3]), "r"(b0v), "r"(b1v))

#define LDSM4(r, addr)                                                                \
    asm volatile("ldmatrix.sync.aligned.m8n8.x4.shared.b16 {%0,%1,%2,%3}, [%4];"      \
        : "=r"((r)[0]), "=r"((r)[1]), "=r"((r)[2]), "=r"((r)[3]) : "r"(addr))

#define CP16(dst, src)                                                                \
    asm volatile("cp.async.cg.shared.global [%0], [%1], 16;" :: "r"(dst), "l"(src))
#define CP_COMMIT() asm volatile("cp.async.commit_group;")
#define CP_WAIT1()  asm volatile("cp.async.wait_group 1;")
#define CP_WAIT0()  asm volatile("cp.async.wait_group 0;")

// ---------------- weight transpose + fp16 hi/lo split ----------------
__global__ void wconv_kernel(const float* __restrict__ W, __half* __restrict__ Th,
                             __half* __restrict__ Tl, int K, int N) {
    __shared__ float t[32][33];
    int n0 = blockIdx.x * 32, k0 = blockIdx.y * 32;
    int tx = threadIdx.x, ty = threadIdx.y;     // (32, 8)
#pragma unroll
    for (int i = 0; i < 4; i++)
        t[ty + i * 8][tx] = W[(size_t)(k0 + ty + i * 8) * N + n0 + tx];
    __syncthreads();
#pragma unroll
    for (int i = 0; i < 4; i++) {
        int n = n0 + ty + i * 8, k = k0 + tx;
        float v = t[tx][ty + i * 8];
        __half h = __float2half_rn(v);
        __half l = __float2half_rn(v - __half2float(h));
        Th[(size_t)n * K + k] = h;
        Tl[(size_t)n * K + k] = l;
    }
}

// ---------------- fp16x3 tensor-core GEMM, 3-stage cp.async pipeline ----------
#define TBM 256
#define TBN 128
#define TKC 32
#define ROWP 80                         // padded row bytes (40 halves)
#define AH_OFF 0
#define AL_OFF (TBM * ROWP)             // 20480
#define WH_OFF (2 * TBM * ROWP)         // 40960
#define WL_OFF (WH_OFF + TBN * ROWP)    // 51200
#define BUF_SZ (WL_OFF + TBN * ROWP)    // 61440
#define NSTG 3
#define SMEM_G (NSTG * BUF_SZ)          // 184320

template <int KTOT, int ADD>
__global__ void __launch_bounds__(256, 1)
hgemm_kernel(const __half* __restrict__ Ah, const __half* __restrict__ Al,
             const __half* __restrict__ Wh, const __half* __restrict__ Wl,
             const float* __restrict__ Rs, float* __restrict__ C, int N) {
    extern __shared__ char smem[];
    const uint32_t sb = smem_u32(smem);
    const int tid = threadIdx.x, wid = tid >> 5, lane = tid & 31;
    const int wm = wid & 3, wn = wid >> 2;
    const int bm = blockIdx.y * TBM, bn = blockIdx.x * TBN;

    float acc[4][8][4];
#pragma unroll
    for (int i = 0; i < 4; i++)
#pragma unroll
        for (int j = 0; j < 8; j++)
#pragma unroll
            for (int k = 0; k < 4; k++) acc[i][j][k] = 0.f;

    const int a_row = lane & 15;
    const int a_k8 = (lane >> 4) << 3;
    const int b_row = (lane & 7) | ((lane >> 4) << 3);
    const int b_k8 = ((lane >> 3) & 1) << 3;

    auto load_chunk = [&](int c, int p) {
        uint32_t base = sb + p * BUF_SZ;
        size_t kof = (size_t)c * TKC;
#pragma unroll
        for (int i = 0; i < 4; i++) {                // A: 1024 x 16B (hi) + (lo)
            int lin = tid + i * 256;
            int r = lin >> 2, q = lin & 3;
            size_t g = (size_t)(bm + r) * KTOT + kof + q * 8;
            uint32_t d = base + AH_OFF + r * ROWP + q * 16;
            CP16(d, Ah + g);
            CP16(d + (AL_OFF - AH_OFF), Al + g);
        }
#pragma unroll
        for (int i = 0; i < 2; i++) {                // W: 512 x 16B (hi) + (lo)
            int lin = tid + i * 256;
            int r = lin >> 2, q = lin & 3;
            size_t g = (size_t)(bn + r) * KTOT + kof + q * 8;
            uint32_t d = base + WH_OFF + r * ROWP + q * 16;
            CP16(d, Wh + g);
            CP16(d + (WL_OFF - WH_OFF), Wl + g);
        }
    };

    auto compute = [&](int p) {
        uint32_t base = sb + p * BUF_SZ;
#pragma unroll
        for (int ks = 0; ks < 2; ks++) {
            uint32_t aH[4][4], aL[4][4];
#pragma unroll
            for (int mt = 0; mt < 4; mt++) {
                uint32_t ra = base + AH_OFF + (wm * 64 + mt * 16 + a_row) * ROWP
                            + (ks * 16 + a_k8) * 2;
                LDSM4(aH[mt], ra);
                LDSM4(aL[mt], ra + (AL_OFF - AH_OFF));
            }
#pragma unroll
            for (int ng = 0; ng < 4; ng++) {
                uint32_t bH[4], bL[4];
                uint32_t rb = base + WH_OFF + (wn * 64 + ng * 16 + b_row) * ROWP
                            + (ks * 16 + b_k8) * 2;
                LDSM4(bH, rb);
                LDSM4(bL, rb + (WL_OFF - WH_OFF));
#pragma unroll
                for (int mt = 0; mt < 4; mt++) {
#pragma unroll
                    for (int j = 0; j < 2; j++) {
                        float* d = acc[mt][ng * 2 + j];
                        MMA16816(d, aH[mt], bH[2 * j], bH[2 * j + 1]);
                        MMA16816(d, aL[mt], bH[2 * j], bH[2 * j + 1]);
                        MMA16816(d, aH[mt], bL[2 * j], bL[2 * j + 1]);
                    }
                }
            }
        }
    };

    constexpr int NCH = KTOT / TKC;
    load_chunk(0, 0); CP_COMMIT();
    load_chunk(1, 1); CP_COMMIT();
    for (int c = 0; c < NCH; c++) {
        if (c + 1 < NCH) CP_WAIT1(); else CP_WAIT0();
        __syncthreads();                  // chunk c resident; all warps done with buf (c+2)%3
        if (c + 2 < NCH) { load_chunk(c + 2, (c + 2) % NSTG); CP_COMMIT(); }
        compute(c % NSTG);
    }

    // epilogue
    const int mrow = lane >> 2, ncol = (lane & 3) * 2;
#pragma unroll
    for (int mt = 0; mt < 4; mt++) {
        int m0 = bm + wm * 64 + mt * 16 + mrow;
#pragma unroll
        for (int n8 = 0; n8 < 8; n8++) {
            int n0 = bn + wn * 64 + n8 * 8 + ncol;
            float* d = acc[mt][n8];
            float2 v0 = make_float2(d[0], d[1]);
            float2 v1 = make_float2(d[2], d[3]);
            if (ADD) {
                float2 r0 = *(const float2*)(Rs + (size_t)m0 * N + n0);
                float2 r1 = *(const float2*)(Rs + (size_t)(m0 + 8) * N + n0);
                v0.x += r0.x; v0.y += r0.y; v1.x += r1.x; v1.y += r1.y;
            }
            *(float2*)(C + (size_t)m0 * N + n0) = v0;
            *(float2*)(C + (size_t)(m0 + 8) * N + n0) = v1;
        }
    }
}

// ---------------- fused span-embed + rms1 -> x1 (fp32) + (ah, al) ------------
__global__ void span_rms_kernel(const float* __restrict__ x, const int* __restrict__ span,
                                const float* __restrict__ w_span, const float* __restrict__ wn) {
    int row = blockIdx.x;
    int t = threadIdx.x;                  // 256, 1 float4 each
    float se = log1pf((float)span[row]);
    float4 a = ((const float4*)(x + (size_t)row * DD))[t];
    float4 w = ((const float4*)w_span)[t];
    a.x += se * w.x; a.y += se * w.y; a.z += se * w.z; a.w += se * w.w;
    ((float4*)(g_x1 + (size_t)row * DD))[t] = a;
    float ss = a.x * a.x + a.y * a.y + a.z * a.z + a.w * a.w;
    for (int off = 16; off > 0; off >>= 1) ss += __shfl_xor_sync(0xffffffffu, ss, off);
    __shared__ float red[8];
    if ((t & 31) == 0) red[t >> 5] = ss;
    __syncthreads();
    if (t < 8) {
        float v = red[t];
        for (int off = 4; off > 0; off >>= 1) v += __shfl_xor_sync(0xffu, v, off);
        if (t == 0) red[0] = v;
    }
    __syncthreads();
    float scale = rsqrtf(red[0] / (float)DD + 1e-6f);
    float4 wv = ((const float4*)wn)[t];
    float4 h = make_float4(a.x * scale * wv.x, a.y * scale * wv.y,
                           a.z * scale * wv.z, a.w * scale * wv.w);
    uint2 hi, lo; split4(h, hi, lo);
    ((uint2*)g_ah)[row * 256 + t] = hi;
    ((uint2*)g_al)[row * 256 + t] = lo;
}

// ---------------- rms2 -> (ah, al) only ----------------
__global__ void rms_split_kernel(const float* __restrict__ xin, const float* __restrict__ wn) {
    int row = blockIdx.x;
    int t = threadIdx.x;
    float4 a = ((const float4*)(xin + (size_t)row * DD))[t];
    float ss = a.x * a.x + a.y * a.y + a.z * a.z + a.w * a.w;
    for (int off = 16; off > 0; off >>= 1) ss += __shfl_xor_sync(0xffffffffu, ss, off);
    __shared__ float red[8];
    if ((t & 31) == 0) red[t >> 5] = ss;
    __syncthreads();
    if (t < 8) {
        float v = red[t];
        for (int off = 4; off > 0; off >>= 1) v += __shfl_xor_sync(0xffu, v, off);
        if (t == 0) red[0] = v;
    }
    __syncthreads();
    float scale = rsqrtf(red[0] / (float)DD + 1e-6f);
    float4 wv = ((const float4*)wn)[t];
    float4 h = make_float4(a.x * scale * wv.x, a.y * scale * wv.y,
                           a.z * scale * wv.z, a.w * scale * wv.w);
    uint2 hi, lo; split4(h, hi, lo);
    ((uint2*)g_ah)[row * 256 + t] = hi;
    ((uint2*)g_al)[row * 256 + t] = lo;
}

// ---------------- fused RoPE + windowed attention -> o as (ah, al) -----------
__global__ void attn_rope_kernel(const float* __restrict__ q, const float* __restrict__ k,
                                 const float* __restrict__ v, const int* __restrict__ pos,
                                 const float* __restrict__ freqs) {
    int blk = blockIdx.x;
    int head = blk % HH;
    int win = (blk / HH) % NWIN;
    int b = blk / (HH * NWIN);
    int s0 = b * SS + win * WINW;

    __shared__ float sq[16][68], sk[16][68], sv[16][68], sp[16][17];
    int tid = threadIdx.x;                // 256
    {
        int r = tid >> 4, c = (tid & 15) * 4;
        size_t g = (size_t)(s0 + r) * DD + head * DHH + c;
        *(float4*)(&sq[r][c]) = *(const float4*)(q + g);
        *(float4*)(&sk[r][c]) = *(const float4*)(k + g);
        *(float4*)(&sv[r][c]) = *(const float4*)(v + g);
    }
    __syncthreads();
    // RoPE in smem: 16 rows x 32 pairs = 512 items
#pragma unroll
    for (int i = tid; i < 512; i += 256) {
        int r = i >> 5, dp = i & 31;
        float ang = (float)pos[s0 + r] * freqs[dp];
        float c = cosf(ang), s = sinf(ang);
        float a = sq[r][dp], b2 = sq[r][dp + 32];
        sq[r][dp] = a * c - b2 * s; sq[r][dp + 32] = a * s + b2 * c;
        a = sk[r][dp]; b2 = sk[r][dp + 32];
        sk[r][dp] = a * c - b2 * s; sk[r][dp + 32] = a * s + b2 * c;
    }
    __syncthreads();

    int qi = tid >> 4, ki = tid & 15;
    float sc = 0.f;
#pragma unroll
    for (int d = 0; d < DHH; d++) sc += sq[qi][d] * sk[ki][d];
    sc *= 0.125f;
    float m = sc;
#pragma unroll
    for (int off = 8; off > 0; off >>= 1) m = fmaxf(m, __shfl_xor_sync(0xffffffffu, m, off, 16));
    float e = expf(sc - m);
    float su = e;
#pragma unroll
    for (int off = 8; off > 0; off >>= 1) su += __shfl_xor_sync(0xffffffffu, su, off, 16);
    sp[qi][ki] = e / su;
    __syncthreads();

    int dg = tid & 15;
    float4 acc = make_float4(0.f, 0.f, 0.f, 0.f);
#pragma unroll
    for (int kk = 0; kk < 16; kk++) {
        float p = sp[qi][kk];
        acc.x += p * sv[kk][dg * 4 + 0];
        acc.y += p * sv[kk][dg * 4 + 1];
        acc.z += p * sv[kk][dg * 4 + 2];
        acc.w += p * sv[kk][dg * 4 + 3];
    }
    size_t go = (size_t)(s0 + qi) * DD + head * DHH + dg * 4;   // multiple of 4
    uint2 hi, lo; split4(acc, hi, lo);
    *(uint2*)(g_ah + go) = hi;
    *(uint2*)(g_al + go) = lo;
}

// ---------------- silu(f1)*f2 -> (ah, al) ----------------
__global__ void silu_split_kernel(int n4) {
    int i = blockIdx.x * 256 + threadIdx.x;
    if (i >= n4) return;
    float4 a = ((const float4*)g_f1)[i];
    float4 b = ((const float4*)g_f2)[i];
    a.x = a.x / (1.f + expf(-a.x)) * b.x;
    a.y = a.y / (1.f + expf(-a.y)) * b.y;
    a.z = a.z / (1.f + expf(-a.z)) * b.z;
    a.w = a.w / (1.f + expf(-a.w)) * b.w;
    uint2 hi, lo; split4(a, hi, lo);
    ((uint2*)g_ah)[i] = hi;
    ((uint2*)g_al)[i] = lo;
}

// ---------------- SGEMM 64x64 fp32 (metric GEMM, N=64) ----------------
__global__ void sgemm64_kernel(const float* __restrict__ A, const float* __restrict__ W,
                               float* __restrict__ C, int M, int N, int K) {
    __shared__ float As[16][68];
    __shared__ float Ws[16][68];
    int tx = threadIdx.x, ty = threadIdx.y;
    int tid = ty * 16 + tx;
    int bm = blockIdx.y * 64, bn = blockIdx.x * 64;
    float acc[4][4] = {};
    for (int k0 = 0; k0 < K; k0 += 16) {
        {
            int r = tid >> 2, c = (tid & 3) * 4;
            float4 a = *(const float4*)(A + (size_t)(bm + r) * K + k0 + c);
            As[c + 0][r] = a.x; As[c + 1][r] = a.y; As[c + 2][r] = a.z; As[c + 3][r] = a.w;
        }
        {
            int r = tid >> 4, c = (tid & 15) * 4;
            *(float4*)(&Ws[r][c]) = *(const float4*)(W + (size_t)(k0 + r) * N + bn + c);
        }
        __syncthreads();
#pragma unroll
        for (int kk = 0; kk < 16; kk++) {
            float4 a = *(const float4*)(&As[kk][ty * 4]);
            float4 b = *(const float4*)(&Ws[kk][tx * 4]);
            float av[4] = {a.x, a.y, a.z, a.w};
            float bw[4] = {b.x, b.y, b.z, b.w};
#pragma unroll
            for (int i = 0; i < 4; i++)
#pragma unroll
                for (int j = 0; j < 4; j++) acc[i][j] += av[i] * bw[j];
        }
        __syncthreads();
    }
#pragma unroll
    for (int i = 0; i < 4; i++) {
        int m = bm + ty * 4 + i;
#pragma unroll
        for (int j = 0; j < 4; j++) C[(size_t)m * N + bn + tx * 4 + j] = acc[i][j];
    }
}

// ---------------- metric normalization ----------------
__global__ void norm_metric_kernel() {
    int row = blockIdx.x;
    int t = threadIdx.x;                  // 32
    float* mr = g_metric + (size_t)row * GMD;
    float a = mr[t], b = mr[t + 32];
    float ss = a * a + b * b;
#pragma unroll
    for (int off = 16; off > 0; off >>= 1) ss += __shfl_xor_sync(0xffffffffu, ss, off);
    float inv = 1.f / (sqrtf(ss) + 1e-6f);
    mr[t] = a * inv; mr[t + 32] = b * inv;
}

// ---------------- real[b,s] = sum_j source[b,s,j]*pad[b,j] > 0 ----------------
__global__ void real_kernel(const float* __restrict__ source, const float* __restrict__ pad) {
    int row = blockIdx.x;
    int b = row / SS;
    const float* sr = source + (size_t)row * SS;
    const float* pr = pad + (size_t)b * SS;
    float su = 0.f;
    for (int j = threadIdx.x; j < SS; j += 256) su += sr[j] * pr[j];
    for (int off = 16; off > 0; off >>= 1) su += __shfl_xor_sync(0xffffffffu, su, off);
    __shared__ float red[8];
    if ((threadIdx.x & 31) == 0) red[threadIdx.x >> 5] = su;
    __syncthreads();
    if (threadIdx.x == 0) {
        float tot = 0.f;
        for (int i = 0; i < 8; i++) tot += red[i];
        g_real[row] = (tot > 0.f) ? 1 : 0;
    }
}

// ---------------- sim[b,p] ----------------
__global__ void sim_kernel() {
    int bp = blockIdx.x;
    int b = bp / PP, p = bp % PP;
    int t = threadIdx.x;                  // 32
    const float* me = g_metric + ((size_t)b * SS + 2 * p) * GMD;
    const float* mo = me + GMD;
    float d = me[t] * mo[t] + me[t + 32] * mo[t + 32];
#pragma unroll
    for (int off = 16; off > 0; off >>= 1) d += __shfl_xor_sync(0xffffffffu, d, off);
    if (t == 0) {
        int ok = g_real[b * SS + 2 * p] & g_real[b * SS + 2 * p + 1];
        g_sim[bp] = ok ? d : -10000.0f;
    }
}

// ---------------- per-batch top-k(512): bitonic sort + flags + prefix scan ----
__global__ void topk_kernel() {
    int b = blockIdx.x;
    int tid = threadIdx.x;                // 1024
    __shared__ float val[1024];
    __shared__ int idx[1024];
    __shared__ int sf[1024];
    __shared__ int sc[1024];
    val[tid] = g_sim[b * PP + tid];
    idx[tid] = tid;
    __syncthreads();
    for (int k = 2; k <= 1024; k <<= 1) {
        for (int j = k >> 1; j > 0; j >>= 1) {
            int ixj = tid ^ j;
            if (ixj > tid) {
                bool dirDesc = ((tid & k) == 0);
                float v1 = val[tid], v2 = val[ixj];
                int i1 = idx[tid], i2 = idx[ixj];
                bool firstHigher = (v1 > v2) || (v1 == v2 && i1 < i2);
                if (dirDesc ? !firstHigher : firstHigher) {
                    val[tid] = v2; val[ixj] = v1;
                    idx[tid] = i2; idx[ixj] = i1;
                }
            }
            __syncthreads();
        }
    }
    sf[tid] = 0;
    __syncthreads();
    if (tid < RR) sf[idx[tid]] = 1;
    __syncthreads();
    int f = sf[tid];
    g_flag[b * PP + tid] = f;
    sc[tid] = f;
    __syncthreads();
    for (int off = 1; off < 1024; off <<= 1) {
        int t = (tid >= off) ? sc[tid - off] : 0;
        __syncthreads();
        sc[tid] += t;
        __syncthreads();
    }
    g_pf[b * PP + tid] = sc[tid] - f;
}

// ---------------- merge + compact + gather all 4 outputs ----------------
__global__ void gather_kernel(const float* __restrict__ source, const int* __restrict__ pos,
                              const int* __restrict__ span, float* __restrict__ out) {
    int b = blockIdx.y, s = blockIdx.x;
    int p = s >> 1;
    int f = g_flag[b * PP + p];
    bool odd = s & 1;
    if (odd && f) return;
    int j = s - g_pf[b * PP + p];
    int tid = threadIdx.x;                // 256

    const float* xr = g_x1 + ((size_t)b * SS + s) * DD;
    float* xo = out + X_OUT_OFF + ((size_t)b * KEEPN + j) * DD;
    if (!odd && f) {
        float sze = (float)span[b * SS + s];
        float szo = (float)span[b * SS + s + 1];
        float inv = 1.f / (sze + szo);
        const float* xr2 = xr + DD;
        for (int d = tid; d < DD; d += 256) xo[d] = (sze * xr[d] + szo * xr2[d]) * inv;
    } else {
        for (int d = tid; d < DD; d += 256) xo[d] = xr[d];
    }
    const float* sr = source + ((size_t)b * SS + s) * SS;
    float* so = out + SRC_OUT_OFF + ((size_t)b * KEEPN + j) * SS;
    if (!odd && f) {
        const float* sr2 = sr + SS;
        for (int t = tid; t < SS; t += 256) so[t] = sr[t] + sr2[t];
    } else {
        for (int t = tid; t < SS; t += 256) so[t] = sr[t];
    }
    if (tid == 0) {
        out[POS_OUT_OFF + (size_t)b * KEEPN + j] = (float)pos[b * SS + s];
        int sp = span[b * SS + s];
        if (!odd && f) sp += span[b * SS + s + 1];
        out[SP_OUT_OFF + (size_t)b * KEEPN + j] = (float)sp;
    }
}

// ---------------- launch ----------------
extern "C" void kernel_launch(void* const* d_in, const int* in_sizes, int n_in,
                              void* d_out, int out_size) {
    int p = 0;
    const float* x        = (const float*)d_in[p++];
    const float* source   = (const float*)d_in[p++];
    const int*   pos      = (const int*)  d_in[p++];
    const int*   span     = (const int*)  d_in[p++];
    if (p < n_in && in_sizes[p] == 1) p++;            // scalar r, if passed
    const float* freqs    = (const float*)d_in[p++];
    const float* pad_mask = (const float*)d_in[p++];
    p++;                                               // seq_pad_mask (all true; unused)
    const float* w_span   = (const float*)d_in[p++];
    const float* w_norm1  = (const float*)d_in[p++];
    const float* wq       = (const float*)d_in[p++];
    const float* wk       = (const float*)d_in[p++];
    const float* wv       = (const float*)d_in[p++];
    const float* wo       = (const float*)d_in[p++];
    const float* w_norm2  = (const float*)d_in[p++];
    const float* w1       = (const float*)d_in[p++];
    const float* w3       = (const float*)d_in[p++];
    const float* w2       = (const float*)d_in[p++];
    const float* w_metric = (const float*)d_in[p++];
    float* out = (float*)d_out;

    float *gx1, *gq, *gk, *gv, *gf1, *gf2, *gm;
    cudaGetSymbolAddress((void**)&gx1, g_x1);
    cudaGetSymbolAddress((void**)&gq,  g_q);
    cudaGetSymbolAddress((void**)&gk,  g_k);
    cudaGetSymbolAddress((void**)&gv,  g_v);
    cudaGetSymbolAddress((void**)&gf1, g_f1);
    cudaGetSymbolAddress((void**)&gf2, g_f2);
    cudaGetSymbolAddress((void**)&gm,  g_metric);

    __half *gah, *gal;
    cudaGetSymbolAddress((void**)&gah, g_ah);
    cudaGetSymbolAddress((void**)&gal, g_al);

    __half *wqh, *wql, *wkh, *wkl, *wvh, *wvl, *woh, *wol;
    __half *w1h, *w1l, *w3h, *w3l, *w2h, *w2l;
    cudaGetSymbolAddress((void**)&wqh, g_wqh); cudaGetSymbolAddress((void**)&wql, g_wql);
    cudaGetSymbolAddress((void**)&wkh, g_wkh); cudaGetSymbolAddress((void**)&wkl, g_wkl);
    cudaGetSymbolAddress((void**)&wvh, g_wvh); cudaGetSymbolAddress((void**)&wvl, g_wvl);
    cudaGetSymbolAddress((void**)&woh, g_woh); cudaGetSymbolAddress((void**)&wol, g_wol);
    cudaGetSymbolAddress((void**)&w1h, g_w1h); cudaGetSymbolAddress((void**)&w1l, g_w1l);
    cudaGetSymbolAddress((void**)&w3h, g_w3h); cudaGetSymbolAddress((void**)&w3l, g_w3l);
    cudaGetSymbolAddress((void**)&w2h, g_w2h); cudaGetSymbolAddress((void**)&w2l, g_w2l);

    cudaFuncSetAttribute(hgemm_kernel<1024, 0>, cudaFuncAttributeMaxDynamicSharedMemorySize, SMEM_G);
    cudaFuncSetAttribute(hgemm_kernel<1024, 1>, cudaFuncAttributeMaxDynamicSharedMemorySize, SMEM_G);
    cudaFuncSetAttribute(hgemm_kernel<4096, 1>, cudaFuncAttributeMaxDynamicSharedMemorySize, SMEM_G);

    dim3 wcb(32, 8);
    wconv_kernel<<<dim3(DD / 32, DD / 32), wcb>>>(wq, wqh, wql, DD, DD);
    wconv_kernel<<<dim3(DD / 32, DD / 32), wcb>>>(wk, wkh, wkl, DD, DD);
    wconv_kernel<<<dim3(DD / 32, DD / 32), wcb>>>(wv, wvh, wvl, DD, DD);
    wconv_kernel<<<dim3(DD / 32, DD / 32), wcb>>>(wo, woh, wol, DD, DD);
    wconv_kernel<<<dim3(FFD / 32, DD / 32), wcb>>>(w1, w1h, w1l, DD, FFD);
    wconv_kernel<<<dim3(FFD / 32, DD / 32), wcb>>>(w3, w3h, w3l, DD, FFD);
    wconv_kernel<<<dim3(DD / 32, FFD / 32), wcb>>>(w2, w2h, w2l, FFD, DD);

    const int nF4 = TT * FFD / 4;            // 8M
    dim3 gQ(DD / TBN, TT / TBM);             // (8, 32)
    dim3 gF(FFD / TBN, TT / TBM);            // (32, 32)

    span_rms_kernel<<<TT, 256>>>(x, span, w_span, w_norm1);
    hgemm_kernel<1024, 0><<<gQ, 256, SMEM_G>>>(gah, gal, wqh, wql, nullptr, gq, DD);
    hgemm_kernel<1024, 0><<<gQ, 256, SMEM_G>>>(gah, gal, wkh, wkl, nullptr, gk, DD);
    hgemm_kernel<1024, 0><<<gQ, 256, SMEM_G>>>(gah, gal, wvh, wvl, nullptr, gv, DD);
    attn_rope_kernel<<<BB * NWIN * HH, 256>>>(gq, gk, gv, pos, freqs);
    hgemm_kernel<1024, 1><<<gQ, 256, SMEM_G>>>(gah, gal, woh, wol, gx1, gx1, DD);
    rms_split_kernel<<<TT, 256>>>(gx1, w_norm2);
    hgemm_kernel<1024, 0><<<gF, 256, SMEM_G>>>(gah, gal, w1h, w1l, nullptr, gf1, FFD);
    hgemm_kernel<1024, 0><<<gF, 256, SMEM_G>>>(gah, gal, w3h, w3l, nullptr, gf2, FFD);
    silu_split_kernel<<<nF4 / 256, 256>>>(nF4);
    hgemm_kernel<4096, 1><<<gQ, 256, SMEM_G>>>(gah, gal, w2h, w2l, gx1, gx1, DD);
    sgemm64_kernel<<<dim3(GMD / 64, TT / 64), dim3(16, 16)>>>(gx1, w_metric, gm, TT, GMD, DD);
    norm_metric_kernel<<<TT, 32>>>();
    real_kernel<<<BB * SS, 256>>>(source, pad_mask);
    sim_kernel<<<BB * PP, 32>>>();
    topk_kernel<<<BB, 1024>>>();
    gather_kernel<<<dim3(SS, BB), 256>>>(source, pos, span, out);

    (void)out_size; (void)n_in;
}

// round 8
// speedup vs baseline: 2.4812x; 1.0047x over previous
#include <cuda_runtime.h>
#include <cuda_fp16.h>
#include <math.h>
#include <stdint.h>

// ---------------- problem constants ----------------
#define BB   4
#define SS   2048
#define DD   1024
#define HH   16
#define DHH  64
#define FFD  4096
#define WINW 16
#define GMD  64
#define RR   512
#define NWIN (SS / WINW)          // 128
#define TT   (BB * SS)            // 8192 tokens
#define PP   (SS / 2)             // 1024 pairs per batch
#define KEEPN (SS - RR)           // 1536 kept per batch

// output offsets (float32 concatenation of the 4 outputs)
#define X_OUT_OFF   ((size_t)0)
#define SRC_OUT_OFF ((size_t)BB * KEEPN * DD)
#define POS_OUT_OFF (SRC_OUT_OFF + (size_t)BB * KEEPN * SS)
#define SP_OUT_OFF  (POS_OUT_OFF + (size_t)BB * KEEPN)

// ---------------- scratch (static device buffers; no allocation) --------------
__device__ float g_x1[(size_t)TT * DD];
__device__ float g_q [(size_t)TT * DD];
__device__ float g_k [(size_t)TT * DD];
__device__ float g_v [(size_t)TT * DD];
__device__ float g_f1[(size_t)TT * FFD];     // reused as __half buffer (FFN act hi)
__device__ float g_f2[(size_t)TT * FFD];     // reused as __half buffer (FFN act lo)
__device__ float g_metric[(size_t)TT * GMD];
__device__ float g_sim [BB * PP];
__device__ int   g_flag[BB * PP];
__device__ int   g_pf  [BB * PP];
__device__ int   g_real[BB * SS];

// fp16 hi/lo split activations (width DD only)
__device__ __half g_ah[(size_t)TT * DD];
__device__ __half g_al[(size_t)TT * DD];

// transposed fp16 hi/lo weights: Wt[n][k]
__device__ __half g_wqh[DD * DD],  g_wql[DD * DD];
__device__ __half g_wkh[DD * DD],  g_wkl[DD * DD];
__device__ __half g_wvh[DD * DD],  g_wvl[DD * DD];
__device__ __half g_woh[DD * DD],  g_wol[DD * DD];
__device__ __half g_w1h[(size_t)FFD * DD], g_w1l[(size_t)FFD * DD];
__device__ __half g_w3h[(size_t)FFD * DD], g_w3l[(size_t)FFD * DD];
__device__ __half g_w2h[(size_t)DD * FFD], g_w2l[(size_t)DD * FFD];

// ---------------- helpers ----------------
__device__ __forceinline__ uint32_t smem_u32(const void* p) {
    uint32_t a;
    asm("{ .reg .u64 t; cvta.to.shared.u64 t, %1; cvt.u32.u64 %0, t; }" : "=r"(a) : "l"(p));
    return a;
}
__device__ __forceinline__ uint32_t pkh(__half a, __half b) {
    __half2 t; t.x = a; t.y = b;
    return *(uint32_t*)&t;
}
__device__ __forceinline__ void split4(float4 a, uint2& hi, uint2& lo) {
    __half h0 = __float2half_rn(a.x), h1 = __float2half_rn(a.y);
    __half h2 = __float2half_rn(a.z), h3 = __float2half_rn(a.w);
    __half l0 = __float2half_rn(a.x - __half2float(h0));
    __half l1 = __float2half_rn(a.y - __half2float(h1));
    __half l2 = __float2half_rn(a.z - __half2float(h2));
    __half l3 = __float2half_rn(a.w - __half2float(h3));
    hi = make_uint2(pkh(h0, h1), pkh(h2, h3));
    lo = make_uint2(pkh(l0, l1), pkh(l2, l3));
}
__device__ __forceinline__ void split2(float x, float y, uint32_t& hi, uint32_t& lo) {
    __half h0 = __float2half_rn(x), h1 = __float2half_rn(y);
    __half l0 = __float2half_rn(x - __half2float(h0));
    __half l1 = __float2half_rn(y - __half2float(h1));
    hi = pkh(h0, h1);
    lo = pkh(l0, l1);
}
__device__ __forceinline__ float siluf(float v) { return v / (1.f + expf(-v)); }

#define MMA16816(d, a, b0v, b1v)                                                      \
    asm volatile("mma.sync.aligned.m16n8k16.row.col.f32.f16.f16.f32 "                 \
        "{%0,%1,%2,%3}, {%4,%5,%6,%7}, {%8,%9}, {%0,%1,%2,%3};"                       \
        : "+f"((d)[0]), "+f"((d)[1]), "+f"((d)[2]), "+f"((d)[3])                      \
        : "r"((a)[0]), "r"((a)[1]), "r"((a)[2]), "r"((a)[3]), "r"(b0v), "r"(b1v))

#define LDSM4(r, addr)                                                                \
    asm volatile("ldmatrix.sync.aligned.m8n8.x4.shared.b16 {%0,%1,%2,%3}, [%4];"      \
        : "=r"((r)[0]), "=r"((r)[1]), "=r"((r)[2]), "=r"((r)[3]) : "r"(addr))

#define CP16(dst, src)                                                                \
    asm volatile("cp.async.cg.shared.global [%0], [%1], 16;" :: "r"(dst), "l"(src))
#define CP_COMMIT() asm volatile("cp.async.commit_group;")
#define CP_WAIT1()  asm volatile("cp.async.wait_group 1;")
#define CP_WAIT0()  asm volatile("cp.async.wait_group 0;")

// ---------------- weight transpose + fp16 hi/lo split ----------------
__global__ void wconv_kernel(const float* __restrict__ W, __half* __restrict__ Th,
                             __half* __restrict__ Tl, int K, int N) {
    __shared__ float t[32][33];
    int n0 = blockIdx.x * 32, k0 = blockIdx.y * 32;
    int tx = threadIdx.x, ty = threadIdx.y;     // (32, 8)
#pragma unroll
    for (int i = 0; i < 4; i++)
        t[ty + i * 8][tx] = W[(size_t)(k0 + ty + i * 8) * N + n0 + tx];
    __syncthreads();
#pragma unroll
    for (int i = 0; i < 4; i++) {
        int n = n0 + ty + i * 8, k = k0 + tx;
        float v = t[tx][ty + i * 8];
        __half h = __float2half_rn(v);
        __half l = __float2half_rn(v - __half2float(h));
        Th[(size_t)n * K + k] = h;
        Tl[(size_t)n * K + k] = l;
    }
}

// ---------------- fp16x3 tensor-core GEMM, 3-stage cp.async pipeline ----------
#define TBM 256
#define TBN 128
#define TKC 32
#define ROWP 80
#define AH_OFF 0
#define AL_OFF (TBM * ROWP)             // 20480
#define WH_OFF (2 * TBM * ROWP)         // 40960
#define WL_OFF (WH_OFF + TBN * ROWP)    // 51200
#define BUF_SZ (WL_OFF + TBN * ROWP)    // 61440
#define NSTG 3
#define SMEM_G (NSTG * BUF_SZ)          // 184320

template <int KTOT, int ADD>
__global__ void __launch_bounds__(256, 1)
hgemm_kernel(const __half* __restrict__ Ah, const __half* __restrict__ Al,
             const __half* __restrict__ Wh, const __half* __restrict__ Wl,
             const float* __restrict__ Rs, float* __restrict__ C, int N) {
    extern __shared__ char smem[];
    const uint32_t sb = smem_u32(smem);
    const int tid = threadIdx.x, wid = tid >> 5, lane = tid & 31;
    const int wm = wid & 3, wn = wid >> 2;
    const int bm = blockIdx.y * TBM, bn = blockIdx.x * TBN;

    float acc[4][8][4];
#pragma unroll
    for (int i = 0; i < 4; i++)
#pragma unroll
        for (int j = 0; j < 8; j++)
#pragma unroll
            for (int k = 0; k < 4; k++) acc[i][j][k] = 0.f;

    const int a_row = lane & 15;
    const int a_k8 = (lane >> 4) << 3;
    const int b_row = (lane & 7) | ((lane >> 4) << 3);
    const int b_k8 = ((lane >> 3) & 1) << 3;

    auto load_chunk = [&](int c, int p) {
        uint32_t base = sb + p * BUF_SZ;
        size_t kof = (size_t)c * TKC;
#pragma unroll
        for (int i = 0; i < 4; i++) {
            int lin = tid + i * 256;
            int r = lin >> 2, q = lin & 3;
            size_t g = (size_t)(bm + r) * KTOT + kof + q * 8;
            uint32_t d = base + AH_OFF + r * ROWP + q * 16;
            CP16(d, Ah + g);
            CP16(d + (AL_OFF - AH_OFF), Al + g);
        }
#pragma unroll
        for (int i = 0; i < 2; i++) {
            int lin = tid + i * 256;
            int r = lin >> 2, q = lin & 3;
            size_t g = (size_t)(bn + r) * KTOT + kof + q * 8;
            uint32_t d = base + WH_OFF + r * ROWP + q * 16;
            CP16(d, Wh + g);
            CP16(d + (WL_OFF - WH_OFF), Wl + g);
        }
    };

    auto compute = [&](int p) {
        uint32_t base = sb + p * BUF_SZ;
#pragma unroll
        for (int ks = 0; ks < 2; ks++) {
            uint32_t aH[4][4], aL[4][4];
#pragma unroll
            for (int mt = 0; mt < 4; mt++) {
                uint32_t ra = base + AH_OFF + (wm * 64 + mt * 16 + a_row) * ROWP
                            + (ks * 16 + a_k8) * 2;
                LDSM4(aH[mt], ra);
                LDSM4(aL[mt], ra + (AL_OFF - AH_OFF));
            }
#pragma unroll
            for (int ng = 0; ng < 4; ng++) {
                uint32_t bH[4], bL[4];
                uint32_t rb = base + WH_OFF + (wn * 64 + ng * 16 + b_row) * ROWP
                            + (ks * 16 + b_k8) * 2;
                LDSM4(bH, rb);
                LDSM4(bL, rb + (WL_OFF - WH_OFF));
#pragma unroll
                for (int mt = 0; mt < 4; mt++) {
#pragma unroll
                    for (int j = 0; j < 2; j++) {
                        float* d = acc[mt][ng * 2 + j];
                        MMA16816(d, aH[mt], bH[2 * j], bH[2 * j + 1]);
                        MMA16816(d, aL[mt], bH[2 * j], bH[2 * j + 1]);
                        MMA16816(d, aH[mt], bL[2 * j], bL[2 * j + 1]);
                    }
                }
            }
        }
    };

    constexpr int NCH = KTOT / TKC;
    load_chunk(0, 0); CP_COMMIT();
    load_chunk(1, 1); CP_COMMIT();
    for (int c = 0; c < NCH; c++) {
        if (c + 1 < NCH) CP_WAIT1(); else CP_WAIT0();
        __syncthreads();
        if (c + 2 < NCH) { load_chunk(c + 2, (c + 2) % NSTG); CP_COMMIT(); }
        compute(c % NSTG);
    }

    const int mrow = lane >> 2, ncol = (lane & 3) * 2;
#pragma unroll
    for (int mt = 0; mt < 4; mt++) {
        int m0 = bm + wm * 64 + mt * 16 + mrow;
#pragma unroll
        for (int n8 = 0; n8 < 8; n8++) {
            int n0 = bn + wn * 64 + n8 * 8 + ncol;
            float* d = acc[mt][n8];
            float2 v0 = make_float2(d[0], d[1]);
            float2 v1 = make_float2(d[2], d[3]);
            if (ADD) {
                float2 r0 = *(const float2*)(Rs + (size_t)m0 * N + n0);
                float2 r1 = *(const float2*)(Rs + (size_t)(m0 + 8) * N + n0);
                v0.x += r0.x; v0.y += r0.y; v1.x += r1.x; v1.y += r1.y;
            }
            *(float2*)(C + (size_t)m0 * N + n0) = v0;
            *(float2*)(C + (size_t)(m0 + 8) * N + n0) = v1;
        }
    }
}

// ---------------- fused dual FFN GEMM: f1 = h@w1, f2 = h@w3, out = silu(f1)*f2
#define D_AH 0
#define D_AL 10240
#define D_W1H 20480
#define D_W1L 30720
#define D_W3H 40960
#define D_W3L 51200
#define DBUF 61440
#define DSMEM (NSTG * DBUF)             // 184320

__global__ void __launch_bounds__(256, 1)
dualffn_kernel(const __half* __restrict__ Ah, const __half* __restrict__ Al,
               const __half* __restrict__ W1h, const __half* __restrict__ W1l,
               const __half* __restrict__ W3h, const __half* __restrict__ W3l,
               __half* __restrict__ Bh, __half* __restrict__ Bl) {
    extern __shared__ char smem[];
    const uint32_t sb = smem_u32(smem);
    const int tid = threadIdx.x, wid = tid >> 5, lane = tid & 31;
    const int wm = wid & 1, wn = wid >> 1;           // 2 x 4 warps, warp tile 64x32
    const int bm = blockIdx.y * 128, bn = blockIdx.x * 128;

    float acc[2][4][4][4];
#pragma unroll
    for (int w = 0; w < 2; w++)
#pragma unroll
        for (int i = 0; i < 4; i++)
#pragma unroll
            for (int j = 0; j < 4; j++)
#pragma unroll
                for (int k = 0; k < 4; k++) acc[w][i][j][k] = 0.f;

    const int a_row = lane & 15;
    const int a_k8 = (lane >> 4) << 3;
    const int b_row = (lane & 7) | ((lane >> 4) << 3);
    const int b_k8 = ((lane >> 3) & 1) << 3;

    auto load_chunk = [&](int c, int p) {
        uint32_t base = sb + p * DBUF;
        size_t kof = (size_t)c * TKC;
#pragma unroll
        for (int i = 0; i < 2; i++) {
            int lin = tid + i * 256;
            int r = lin >> 2, q = lin & 3;
            size_t g = (size_t)(bm + r) * DD + kof + q * 8;
            uint32_t d = base + D_AH + r * ROWP + q * 16;
            CP16(d, Ah + g);
            CP16(d + (D_AL - D_AH), Al + g);
        }
#pragma unroll
        for (int i = 0; i < 2; i++) {
            int lin = tid + i * 256;
            int r = lin >> 2, q = lin & 3;
            size_t g = (size_t)(bn + r) * DD + kof + q * 8;
            uint32_t d = base + D_W1H + r * ROWP + q * 16;
            CP16(d, W1h + g);
            CP16(d + (D_W1L - D_W1H), W1l + g);
        }
#pragma unroll
        for (int i = 0; i < 2; i++) {
            int lin = tid + i * 256;
            int r = lin >> 2, q = lin & 3;
            size_t g = (size_t)(bn + r) * DD + kof + q * 8;
            uint32_t d = base + D_W3H + r * ROWP + q * 16;
            CP16(d, W3h + g);
            CP16(d + (D_W3L - D_W3H), W3l + g);
        }
    };

    auto compute = [&](int p) {
        uint32_t base = sb + p * DBUF;
#pragma unroll
        for (int ks = 0; ks < 2; ks++) {
            uint32_t aH[4][4], aL[4][4];
#pragma unroll
            for (int mt = 0; mt < 4; mt++) {
                uint32_t ra = base + D_AH + (wm * 64 + mt * 16 + a_row) * ROWP
                            + (ks * 16 + a_k8) * 2;
                LDSM4(aH[mt], ra);
                LDSM4(aL[mt], ra + (D_AL - D_AH));
            }
#pragma unroll
            for (int w = 0; w < 2; w++) {
                uint32_t wbase = base + (w ? D_W3H : D_W1H);
#pragma unroll
                for (int ng = 0; ng < 2; ng++) {
                    uint32_t bH[4], bL[4];
                    uint32_t rb = wbase + (wn * 32 + ng * 16 + b_row) * ROWP
                                + (ks * 16 + b_k8) * 2;
                    LDSM4(bH, rb);
                    LDSM4(bL, rb + 10240);
#pragma unroll
                    for (int mt = 0; mt < 4; mt++) {
#pragma unroll
                        for (int j = 0; j < 2; j++) {
                            float* d = acc[w][mt][ng * 2 + j];
                            MMA16816(d, aH[mt], bH[2 * j], bH[2 * j + 1]);
                            MMA16816(d, aL[mt], bH[2 * j], bH[2 * j + 1]);
                            MMA16816(d, aH[mt], bL[2 * j], bL[2 * j + 1]);
                        }
                    }
                }
            }
        }
    };

    constexpr int NCH = DD / TKC;                    // 32
    load_chunk(0, 0); CP_COMMIT();
    load_chunk(1, 1); CP_COMMIT();
    for (int c = 0; c < NCH; c++) {
        if (c + 1 < NCH) CP_WAIT1(); else CP_WAIT0();
        __syncthreads();
        if (c + 2 < NCH) { load_chunk(c + 2, (c + 2) % NSTG); CP_COMMIT(); }
        compute(c % NSTG);
    }

    const int mrow = lane >> 2, ncol = (lane & 3) * 2;
#pragma unroll
    for (int mt = 0; mt < 4; mt++) {
        int m0 = bm + wm * 64 + mt * 16 + mrow;
#pragma unroll
        for (int n8 = 0; n8 < 4; n8++) {
            int n0 = bn + wn * 32 + n8 * 8 + ncol;
            float* d1 = acc[0][mt][n8];
            float* d3 = acc[1][mt][n8];
            float g0 = siluf(d1[0]) * d3[0];
            float g1 = siluf(d1[1]) * d3[1];
            float g2 = siluf(d1[2]) * d3[2];
            float g3 = siluf(d1[3]) * d3[3];
            uint32_t hi, lo;
            split2(g0, g1, hi, lo);
            *(uint32_t*)(Bh + (size_t)m0 * FFD + n0) = hi;
            *(uint32_t*)(Bl + (size_t)m0 * FFD + n0) = lo;
            split2(g2, g3, hi, lo);
            *(uint32_t*)(Bh + (size_t)(m0 + 8) * FFD + n0) = hi;
            *(uint32_t*)(Bl + (size_t)(m0 + 8) * FFD + n0) = lo;
        }
    }
}

// ---------------- fused span-embed + rms1 -> x1 (fp32) + (ah, al) ------------
__global__ void span_rms_kernel(const float* __restrict__ x, const int* __restrict__ span,
                                const float* __restrict__ w_span, const float* __restrict__ wn) {
    int row = blockIdx.x;
    int t = threadIdx.x;                  // 256, 1 float4 each
    float se = log1pf((float)span[row]);
    float4 a = ((const float4*)(x + (size_t)row * DD))[t];
    float4 w = ((const float4*)w_span)[t];
    a.x += se * w.x; a.y += se * w.y; a.z += se * w.z; a.w += se * w.w;
    ((float4*)(g_x1 + (size_t)row * DD))[t] = a;
    float ss = a.x * a.x + a.y * a.y + a.z * a.z + a.w * a.w;
    for (int off = 16; off > 0; off >>= 1) ss += __shfl_xor_sync(0xffffffffu, ss, off);
    __shared__ float red[8];
    if ((t & 31) == 0) red[t >> 5] = ss;
    __syncthreads();
    if (t < 8) {
        float v = red[t];
        for (int off = 4; off > 0; off >>= 1) v += __shfl_xor_sync(0xffu, v, off);
        if (t == 0) red[0] = v;
    }
    __syncthreads();
    float scale = rsqrtf(red[0] / (float)DD + 1e-6f);
    float4 wv = ((const float4*)wn)[t];
    float4 h = make_float4(a.x * scale * wv.x, a.y * scale * wv.y,
                           a.z * scale * wv.z, a.w * scale * wv.w);
    uint2 hi, lo; split4(h, hi, lo);
    ((uint2*)g_ah)[row * 256 + t] = hi;
    ((uint2*)g_al)[row * 256 + t] = lo;
}

// ---------------- rms2 -> (ah, al) only ----------------
__global__ void rms_split_kernel(const float* __restrict__ xin, const float* __restrict__ wn) {
    int row = blockIdx.x;
    int t = threadIdx.x;
    float4 a = ((const float4*)(xin + (size_t)row * DD))[t];
    float ss = a.x * a.x + a.y * a.y + a.z * a.z + a.w * a.w;
    for (int off = 16; off > 0; off >>= 1) ss += __shfl_xor_sync(0xffffffffu, ss, off);
    __shared__ float red[8];
    if ((t & 31) == 0) red[t >> 5] = ss;
    __syncthreads();
    if (t < 8) {
        float v = red[t];
        for (int off = 4; off > 0; off >>= 1) v += __shfl_xor_sync(0xffu, v, off);
        if (t == 0) red[0] = v;
    }
    __syncthreads();
    float scale = rsqrtf(red[0] / (float)DD + 1e-6f);
    float4 wv = ((const float4*)wn)[t];
    float4 h = make_float4(a.x * scale * wv.x, a.y * scale * wv.y,
                           a.z * scale * wv.z, a.w * scale * wv.w);
    uint2 hi, lo; split4(h, hi, lo);
    ((uint2*)g_ah)[row * 256 + t] = hi;
    ((uint2*)g_al)[row * 256 + t] = lo;
}

// ---------------- fused RoPE + windowed attention -> o as (ah, al) -----------
__global__ void attn_rope_kernel(const float* __restrict__ q, const float* __restrict__ k,
                                 const float* __restrict__ v, const int* __restrict__ pos,
                                 const float* __restrict__ freqs) {
    int blk = blockIdx.x;
    int head = blk % HH;
    int win = (blk / HH) % NWIN;
    int b = blk / (HH * NWIN);
    int s0 = b * SS + win * WINW;

    __shared__ float sq[16][68], sk[16][68], sv[16][68], sp[16][17];
    int tid = threadIdx.x;                // 256
    {
        int r = tid >> 4, c = (tid & 15) * 4;
        size_t g = (size_t)(s0 + r) * DD + head * DHH + c;
        *(float4*)(&sq[r][c]) = *(const float4*)(q + g);
        *(float4*)(&sk[r][c]) = *(const float4*)(k + g);
        *(float4*)(&sv[r][c]) = *(const float4*)(v + g);
    }
    __syncthreads();
#pragma unroll
    for (int i = tid; i < 512; i += 256) {
        int r = i >> 5, dp = i & 31;
        float ang = (float)pos[s0 + r] * freqs[dp];
        float c = cosf(ang), s = sinf(ang);
        float a = sq[r][dp], b2 = sq[r][dp + 32];
        sq[r][dp] = a * c - b2 * s; sq[r][dp + 32] = a * s + b2 * c;
        a = sk[r][dp]; b2 = sk[r][dp + 32];
        sk[r][dp] = a * c - b2 * s; sk[r][dp + 32] = a * s + b2 * c;
    }
    __syncthreads();

    int qi = tid >> 4, ki = tid & 15;
    float sc = 0.f;
#pragma unroll
    for (int d = 0; d < DHH; d++) sc += sq[qi][d] * sk[ki][d];
    sc *= 0.125f;
    float m = sc;
#pragma unroll
    for (int off = 8; off > 0; off >>= 1) m = fmaxf(m, __shfl_xor_sync(0xffffffffu, m, off, 16));
    float e = expf(sc - m);
    float su = e;
#pragma unroll
    for (int off = 8; off > 0; off >>= 1) su += __shfl_xor_sync(0xffffffffu, su, off, 16);
    sp[qi][ki] = e / su;
    __syncthreads();

    int dg = tid & 15;
    float4 acc = make_float4(0.f, 0.f, 0.f, 0.f);
#pragma unroll
    for (int kk = 0; kk < 16; kk++) {
        float p = sp[qi][kk];
        acc.x += p * sv[kk][dg * 4 + 0];
        acc.y += p * sv[kk][dg * 4 + 1];
        acc.z += p * sv[kk][dg * 4 + 2];
        acc.w += p * sv[kk][dg * 4 + 3];
    }
    size_t go = (size_t)(s0 + qi) * DD + head * DHH + dg * 4;
    uint2 hi, lo; split4(acc, hi, lo);
    *(uint2*)(g_ah + go) = hi;
    *(uint2*)(g_al + go) = lo;
}

// ---------------- SGEMM 64x64 fp32 (metric GEMM, N=64) ----------------
__global__ void sgemm64_kernel(const float* __restrict__ A, const float* __restrict__ W,
                               float* __restrict__ C, int M, int N, int K) {
    __shared__ float As[16][68];
    __shared__ float Ws[16][68];
    int tx = threadIdx.x, ty = threadIdx.y;
    int tid = ty * 16 + tx;
    int bm = blockIdx.y * 64, bn = blockIdx.x * 64;
    float acc[4][4] = {};
    for (int k0 = 0; k0 < K; k0 += 16) {
        {
            int r = tid >> 2, c = (tid & 3) * 4;
            float4 a = *(const float4*)(A + (size_t)(bm + r) * K + k0 + c);
            As[c + 0][r] = a.x; As[c + 1][r] = a.y; As[c + 2][r] = a.z; As[c + 3][r] = a.w;
        }
        {
            int r = tid >> 4, c = (tid & 15) * 4;
            *(float4*)(&Ws[r][c]) = *(const float4*)(W + (size_t)(k0 + r) * N + bn + c);
        }
        __syncthreads();
#pragma unroll
        for (int kk = 0; kk < 16; kk++) {
            float4 a = *(const float4*)(&As[kk][ty * 4]);
            float4 b = *(const float4*)(&Ws[kk][tx * 4]);
            float av[4] = {a.x, a.y, a.z, a.w};
            float bw[4] = {b.x, b.y, b.z, b.w};
#pragma unroll
            for (int i = 0; i < 4; i++)
#pragma unroll
                for (int j = 0; j < 4; j++) acc[i][j] += av[i] * bw[j];
        }
        __syncthreads();
    }
#pragma unroll
    for (int i = 0; i < 4; i++) {
        int m = bm + ty * 4 + i;
#pragma unroll
        for (int j = 0; j < 4; j++) C[(size_t)m * N + bn + tx * 4 + j] = acc[i][j];
    }
}

// ---------------- metric normalization ----------------
__global__ void norm_metric_kernel() {
    int row = blockIdx.x;
    int t = threadIdx.x;                  // 32
    float* mr = g_metric + (size_t)row * GMD;
    float a = mr[t], b = mr[t + 32];
    float ss = a * a + b * b;
#pragma unroll
    for (int off = 16; off > 0; off >>= 1) ss += __shfl_xor_sync(0xffffffffu, ss, off);
    float inv = 1.f / (sqrtf(ss) + 1e-6f);
    mr[t] = a * inv; mr[t + 32] = b * inv;
}

// ---------------- real[b,s] = sum_j source[b,s,j]*pad[b,j] > 0 ----------------
__global__ void real_kernel(const float* __restrict__ source, const float* __restrict__ pad) {
    int row = blockIdx.x;
    int b = row / SS;
    const float* sr = source + (size_t)row * SS;
    const float* pr = pad + (size_t)b * SS;
    float su = 0.f;
    for (int j = threadIdx.x; j < SS; j += 256) su += sr[j] * pr[j];
    for (int off = 16; off > 0; off >>= 1) su += __shfl_xor_sync(0xffffffffu, su, off);
    __shared__ float red[8];
    if ((threadIdx.x & 31) == 0) red[threadIdx.x >> 5] = su;
    __syncthreads();
    if (threadIdx.x == 0) {
        float tot = 0.f;
        for (int i = 0; i < 8; i++) tot += red[i];
        g_real[row] = (tot > 0.f) ? 1 : 0;
    }
}

// ---------------- sim[b,p] ----------------
__global__ void sim_kernel() {
    int bp = blockIdx.x;
    int b = bp / PP, p = bp % PP;
    int t = threadIdx.x;                  // 32
    const float* me = g_metric + ((size_t)b * SS + 2 * p) * GMD;
    const float* mo = me + GMD;
    float d = me[t] * mo[t] + me[t + 32] * mo[t + 32];
#pragma unroll
    for (int off = 16; off > 0; off >>= 1) d += __shfl_xor_sync(0xffffffffu, d, off);
    if (t == 0) {
        int ok = g_real[b * SS + 2 * p] & g_real[b * SS + 2 * p + 1];
        g_sim[bp] = ok ? d : -10000.0f;
    }
}

// ---------------- per-batch top-k(512): bitonic sort + flags + prefix scan ----
__global__ void topk_kernel() {
    int b = blockIdx.x;
    int tid = threadIdx.x;                // 1024
    __shared__ float val[1024];
    __shared__ int idx[1024];
    __shared__ int sf[1024];
    __shared__ int sc[1024];
    val[tid] = g_sim[b * PP + tid];
    idx[tid] = tid;
    __syncthreads();
    for (int k = 2; k <= 1024; k <<= 1) {
        for (int j = k >> 1; j > 0; j >>= 1) {
            int ixj = tid ^ j;
            if (ixj > tid) {
                bool dirDesc = ((tid & k) == 0);
                float v1 = val[tid], v2 = val[ixj];
                int i1 = idx[tid], i2 = idx[ixj];
                bool firstHigher = (v1 > v2) || (v1 == v2 && i1 < i2);
                if (dirDesc ? !firstHigher : firstHigher) {
                    val[tid] = v2; val[ixj] = v1;
                    idx[tid] = i2; idx[ixj] = i1;
                }
            }
            __syncthreads();
        }
    }
    sf[tid] = 0;
    __syncthreads();
    if (tid < RR) sf[idx[tid]] = 1;
    __syncthreads();
    int f = sf[tid];
    g_flag[b * PP + tid] = f;
    sc[tid] = f;
    __syncthreads();
    for (int off = 1; off < 1024; off <<= 1) {
        int t = (tid >= off) ? sc[tid - off] : 0;
        __syncthreads();
        sc[tid] += t;
        __syncthreads();
    }
    g_pf[b * PP + tid] = sc[tid] - f;
}

// ---------------- merge + compact + gather all 4 outputs ----------------
__global__ void gather_kernel(const float* __restrict__ source, const int* __restrict__ pos,
                              const int* __restrict__ span, float* __restrict__ out) {
    int b = blockIdx.y, s = blockIdx.x;
    int p = s >> 1;
    int f = g_flag[b * PP + p];
    bool odd = s & 1;
    if (odd && f) return;
    int j = s - g_pf[b * PP + p];
    int tid = threadIdx.x;                // 256

    const float* xr = g_x1 + ((size_t)b * SS + s) * DD;
    float* xo = out + X_OUT_OFF + ((size_t)b * KEEPN + j) * DD;
    if (!odd && f) {
        float sze = (float)span[b * SS + s];
        float szo = (float)span[b * SS + s + 1];
        float inv = 1.f / (sze + szo);
        const float* xr2 = xr + DD;
        for (int d = tid; d < DD; d += 256) xo[d] = (sze * xr[d] + szo * xr2[d]) * inv;
    } else {
        for (int d = tid; d < DD; d += 256) xo[d] = xr[d];
    }
    const float* sr = source + ((size_t)b * SS + s) * SS;
    float* so = out + SRC_OUT_OFF + ((size_t)b * KEEPN + j) * SS;
    if (!odd && f) {
        const float* sr2 = sr + SS;
        for (int t = tid; t < SS; t += 256) so[t] = sr[t] + sr2[t];
    } else {
        for (int t = tid; t < SS; t += 256) so[t] = sr[t];
    }
    if (tid == 0) {
        out[POS_OUT_OFF + (size_t)b * KEEPN + j] = (float)pos[b * SS + s];
        int sp = span[b * SS + s];
        if (!odd && f) sp += span[b * SS + s + 1];
        out[SP_OUT_OFF + (size_t)b * KEEPN + j] = (float)sp;
    }
}

// ---------------- launch ----------------
extern "C" void kernel_launch(void* const* d_in, const int* in_sizes, int n_in,
                              void* d_out, int out_size) {
    int p = 0;
    const float* x        = (const float*)d_in[p++];
    const float* source   = (const float*)d_in[p++];
    const int*   pos      = (const int*)  d_in[p++];
    const int*   span     = (const int*)  d_in[p++];
    if (p < n_in && in_sizes[p] == 1) p++;            // scalar r, if passed
    const float* freqs    = (const float*)d_in[p++];
    const float* pad_mask = (const float*)d_in[p++];
    p++;                                               // seq_pad_mask (all true; unused)
    const float* w_span   = (const float*)d_in[p++];
    const float* w_norm1  = (const float*)d_in[p++];
    const float* wq       = (const float*)d_in[p++];
    const float* wk       = (const float*)d_in[p++];
    const float* wv       = (const float*)d_in[p++];
    const float* wo       = (const float*)d_in[p++];
    const float* w_norm2  = (const float*)d_in[p++];
    const float* w1       = (const float*)d_in[p++];
    const float* w3       = (const float*)d_in[p++];
    const float* w2       = (const float*)d_in[p++];
    const float* w_metric = (const float*)d_in[p++];
    float* out = (float*)d_out;

    float *gx1, *gq, *gk, *gv, *gf1, *gf2, *gm;
    cudaGetSymbolAddress((void**)&gx1, g_x1);
    cudaGetSymbolAddress((void**)&gq,  g_q);
    cudaGetSymbolAddress((void**)&gk,  g_k);
    cudaGetSymbolAddress((void**)&gv,  g_v);
    cudaGetSymbolAddress((void**)&gf1, g_f1);
    cudaGetSymbolAddress((void**)&gf2, g_f2);
    cudaGetSymbolAddress((void**)&gm,  g_metric);

    __half *gah, *gal;
    cudaGetSymbolAddress((void**)&gah, g_ah);
    cudaGetSymbolAddress((void**)&gal, g_al);
    __half* gbh = (__half*)gf1;                       // FFN activation hi
    __half* gbl = (__half*)gf2;                       // FFN activation lo

    __half *wqh, *wql, *wkh, *wkl, *wvh, *wvl, *woh, *wol;
    __half *w1h, *w1l, *w3h, *w3l, *w2h, *w2l;
    cudaGetSymbolAddress((void**)&wqh, g_wqh); cudaGetSymbolAddress((void**)&wql, g_wql);
    cudaGetSymbolAddress((void**)&wkh, g_wkh); cudaGetSymbolAddress((void**)&wkl, g_wkl);
    cudaGetSymbolAddress((void**)&wvh, g_wvh); cudaGetSymbolAddress((void**)&wvl, g_wvl);
    cudaGetSymbolAddress((void**)&woh, g_woh); cudaGetSymbolAddress((void**)&wol, g_wol);
    cudaGetSymbolAddress((void**)&w1h, g_w1h); cudaGetSymbolAddress((void**)&w1l, g_w1l);
    cudaGetSymbolAddress((void**)&w3h, g_w3h); cudaGetSymbolAddress((void**)&w3l, g_w3l);
    cudaGetSymbolAddress((void**)&w2h, g_w2h); cudaGetSymbolAddress((void**)&w2l, g_w2l);

    cudaFuncSetAttribute(hgemm_kernel<1024, 0>, cudaFuncAttributeMaxDynamicSharedMemorySize, SMEM_G);
    cudaFuncSetAttribute(hgemm_kernel<1024, 1>, cudaFuncAttributeMaxDynamicSharedMemorySize, SMEM_G);
    cudaFuncSetAttribute(hgemm_kernel<4096, 1>, cudaFuncAttributeMaxDynamicSharedMemorySize, SMEM_G);
    cudaFuncSetAttribute(dualffn_kernel, cudaFuncAttributeMaxDynamicSharedMemorySize, DSMEM);

    dim3 wcb(32, 8);
    dim3 gQ(DD / TBN, TT / TBM);             // (8, 32)
    dim3 gD(FFD / 128, TT / 128);            // (32, 64)

    // Launch order: index 5 is hgemm_q (ncu -s 5 -c 1 captures it)
    wconv_kernel<<<dim3(DD / 32, DD / 32), wcb>>>(wq, wqh, wql, DD, DD);       // 0
    wconv_kernel<<<dim3(DD / 32, DD / 32), wcb>>>(wk, wkh, wkl, DD, DD);       // 1
    wconv_kernel<<<dim3(DD / 32, DD / 32), wcb>>>(wv, wvh, wvl, DD, DD);       // 2
    wconv_kernel<<<dim3(DD / 32, DD / 32), wcb>>>(wo, woh, wol, DD, DD);       // 3
    span_rms_kernel<<<TT, 256>>>(x, span, w_span, w_norm1);                    // 4
    hgemm_kernel<1024, 0><<<gQ, 256, SMEM_G>>>(gah, gal, wqh, wql, nullptr, gq, DD);  // 5 <- profiled
    hgemm_kernel<1024, 0><<<gQ, 256, SMEM_G>>>(gah, gal, wkh, wkl, nullptr, gk, DD);
    hgemm_kernel<1024, 0><<<gQ, 256, SMEM_G>>>(gah, gal, wvh, wvl, nullptr, gv, DD);
    wconv_kernel<<<dim3(FFD / 32, DD / 32), wcb>>>(w1, w1h, w1l, DD, FFD);
    wconv_kernel<<<dim3(FFD / 32, DD / 32), wcb>>>(w3, w3h, w3l, DD, FFD);
    wconv_kernel<<<dim3(DD / 32, FFD / 32), wcb>>>(w2, w2h, w2l, FFD, DD);
    attn_rope_kernel<<<BB * NWIN * HH, 256>>>(gq, gk, gv, pos, freqs);
    hgemm_kernel<1024, 1><<<gQ, 256, SMEM_G>>>(gah, gal, woh, wol, gx1, gx1, DD);
    rms_split_kernel<<<TT, 256>>>(gx1, w_norm2);
    dualffn_kernel<<<gD, 256, DSMEM>>>(gah, gal, w1h, w1l, w3h, w3l, gbh, gbl);
    hgemm_kernel<4096, 1><<<gQ, 256, SMEM_G>>>(gbh, gbl, w2h, w2l, gx1, gx1, DD);
    sgemm64_kernel<<<dim3(GMD / 64, TT / 64), dim3(16, 16)>>>(gx1, w_metric, gm, TT, GMD, DD);
    norm_metric_kernel<<<TT, 32>>>();
    real_kernel<<<BB * SS, 256>>>(source, pad_mask);
    sim_kernel<<<BB * PP, 32>>>();
    topk_kernel<<<BB, 1024>>>();
    gather_kernel<<<dim3(SS, BB), 256>>>(source, pos, span, out);

    (void)out_size; (void)n_in;
}